// round 1
// baseline (speedup 1.0000x reference)
#include <cuda_runtime.h>
#include <math.h>

// Problem constants (fixed shapes per reference)
#define BB   2
#define SS   4096
#define DD   512
#define HH   8
#define DHH  64
#define MM   (BB*SS)      // 8192 rows

// ---------------- scratch (device globals; no allocations allowed) ----------
__device__ float g_qkv[MM * 1536];   // 50.3 MB
__device__ float g_ctx[MM * DD];     // 16.8 MB
__device__ float g_r1 [MM * DD];     // pre-LN buffers (reused)
__device__ float g_h  [MM * DD];     // LN1 output (needed as MLP residual)
__device__ float g_mid[MM * DD];     // relu(h@w1^T+b1)

// ---------------- SGEMM: C = A @ W^T + bias (+epilogue) ---------------------
// A: [M,K] row-major, W: [N,K] row-major (torch layout), C: [M,N]
// MODE 0: bias; MODE 1: bias + resid; MODE 2: bias + relu
template<int MODE>
__global__ __launch_bounds__(256)
void sgemm_nt(const float* __restrict__ A, const float* __restrict__ W,
              const float* __restrict__ bias, const float* __restrict__ resid,
              float* __restrict__ C, int M, int N, int K)
{
    __shared__ float As[8][128];
    __shared__ float Bs[8][128];
    const int tid  = threadIdx.x;
    const int brow = blockIdx.y * 128;
    const int bcol = blockIdx.x * 128;
    const int lr = tid >> 1;            // 0..127
    const int lc = (tid & 1) << 2;      // 0 or 4
    const float* Ap = A + (size_t)(brow + lr) * K + lc;
    const float* Wp = W + (size_t)(bcol + lr) * K + lc;
    const int tx = tid & 15;            // col group
    const int ty = tid >> 4;            // row group

    float acc[8][8];
#pragma unroll
    for (int i = 0; i < 8; i++)
#pragma unroll
        for (int j = 0; j < 8; j++) acc[i][j] = 0.f;

    for (int k0 = 0; k0 < K; k0 += 8) {
        float4 av = *(const float4*)(Ap + k0);
        float4 wv = *(const float4*)(Wp + k0);
        __syncthreads();
        As[lc+0][lr] = av.x; As[lc+1][lr] = av.y; As[lc+2][lr] = av.z; As[lc+3][lr] = av.w;
        Bs[lc+0][lr] = wv.x; Bs[lc+1][lr] = wv.y; Bs[lc+2][lr] = wv.z; Bs[lc+3][lr] = wv.w;
        __syncthreads();
#pragma unroll
        for (int kk = 0; kk < 8; kk++) {
            float a[8], b[8];
            *(float4*)(a)     = *(const float4*)&As[kk][ty*8];
            *(float4*)(a + 4) = *(const float4*)&As[kk][ty*8 + 4];
            *(float4*)(b)     = *(const float4*)&Bs[kk][tx*8];
            *(float4*)(b + 4) = *(const float4*)&Bs[kk][tx*8 + 4];
#pragma unroll
            for (int i = 0; i < 8; i++)
#pragma unroll
                for (int j = 0; j < 8; j++) acc[i][j] += a[i] * b[j];
        }
    }

#pragma unroll
    for (int i = 0; i < 8; i++) {
        const int row = brow + ty*8 + i;
#pragma unroll
        for (int j4 = 0; j4 < 8; j4 += 4) {
            const int col = bcol + tx*8 + j4;
            float4 bv = *(const float4*)(bias + col);
            float4 o;
            o.x = acc[i][j4+0] + bv.x;
            o.y = acc[i][j4+1] + bv.y;
            o.z = acc[i][j4+2] + bv.z;
            o.w = acc[i][j4+3] + bv.w;
            if (MODE == 1) {
                float4 rv = *(const float4*)(resid + (size_t)row * N + col);
                o.x += rv.x; o.y += rv.y; o.z += rv.z; o.w += rv.w;
            }
            if (MODE == 2) {
                o.x = fmaxf(o.x, 0.f); o.y = fmaxf(o.y, 0.f);
                o.z = fmaxf(o.z, 0.f); o.w = fmaxf(o.w, 0.f);
            }
            *(float4*)(C + (size_t)row * N + col) = o;
        }
    }
}

// ---------------- sliding-window attention ----------------------------------
// One thread == one query row. q and O live in registers; K/V tiles (32 keys)
// live in smem and are read via broadcast (all lanes same address).
// Per-thread online softmax: no cross-thread reductions needed.
__global__ __launch_bounds__(128)
void attn_kernel(const float* __restrict__ qkv, float* __restrict__ ctx,
                 const int* __restrict__ wptr)
{
    __shared__ float Ks[32][68];   // padded: transposed-free broadcast reads
    __shared__ float Vs[32][68];
    __shared__ float Ss[128][33];  // per-thread score staging, conflict-free

    int w = *wptr;
    if (w < 0 || w > 1000000) w = (int)__int_as_float((unsigned)w); // defensive decode

    const int t  = threadIdx.x;        // 0..127
    const int qt = blockIdx.x;         // query tile
    const int h  = blockIdx.y;
    const int b  = blockIdx.z;
    const int q0 = qt * 128;
    const int qi = q0 + t;
    const float scale = rsqrtf((float)DHH);

    float q[64], o[64];
    const float* qp = qkv + ((size_t)(b * SS + qi)) * 1536 + h * DHH;
#pragma unroll
    for (int d4 = 0; d4 < 16; d4++) {
        float4 v = *(const float4*)(qp + 4 * d4);
        q[4*d4+0] = v.x * scale; q[4*d4+1] = v.y * scale;
        q[4*d4+2] = v.z * scale; q[4*d4+3] = v.w * scale;
        o[4*d4+0] = 0.f; o[4*d4+1] = 0.f; o[4*d4+2] = 0.f; o[4*d4+3] = 0.f;
    }

    float m = -1e30f, l = 0.f;
    int kstart = q0 - w;       if (kstart < 0)  kstart = 0;
    int kend   = q0 + 128 + w; if (kend > SS)   kend = SS;

    const int jr = t >> 2;             // key row this thread loads (0..31)
    const int dc = (t & 3) << 4;       // 16-float chunk within head dim

    for (int k0 = kstart; k0 < kend; k0 += 32) {
        __syncthreads();
        {
            const int jg = k0 + jr;
            if (jg < SS) {
                const float* kp = qkv + ((size_t)(b * SS + jg)) * 1536 + 512  + h * DHH + dc;
                const float* vp = kp + 512;
                float4 a0 = *(const float4*)(kp + 0);
                float4 a1 = *(const float4*)(kp + 4);
                float4 a2 = *(const float4*)(kp + 8);
                float4 a3 = *(const float4*)(kp + 12);
                *(float4*)&Ks[jr][dc + 0]  = a0;
                *(float4*)&Ks[jr][dc + 4]  = a1;
                *(float4*)&Ks[jr][dc + 8]  = a2;
                *(float4*)&Ks[jr][dc + 12] = a3;
                float4 c0 = *(const float4*)(vp + 0);
                float4 c1 = *(const float4*)(vp + 4);
                float4 c2 = *(const float4*)(vp + 8);
                float4 c3 = *(const float4*)(vp + 12);
                *(float4*)&Vs[jr][dc + 0]  = c0;
                *(float4*)&Vs[jr][dc + 4]  = c1;
                *(float4*)&Vs[jr][dc + 8]  = c2;
                *(float4*)&Vs[jr][dc + 12] = c3;
            } else {
                float4 z = make_float4(0.f, 0.f, 0.f, 0.f);
                *(float4*)&Ks[jr][dc + 0]  = z; *(float4*)&Ks[jr][dc + 4]  = z;
                *(float4*)&Ks[jr][dc + 8]  = z; *(float4*)&Ks[jr][dc + 12] = z;
                *(float4*)&Vs[jr][dc + 0]  = z; *(float4*)&Vs[jr][dc + 4]  = z;
                *(float4*)&Vs[jr][dc + 8]  = z; *(float4*)&Vs[jr][dc + 12] = z;
            }
        }
        __syncthreads();

        // scores for this key tile (broadcast smem reads, reg-resident q)
        for (int j = 0; j < 32; j++) {
            const float4* kr = (const float4*)&Ks[j][0];
            float s0 = 0.f, s1 = 0.f, s2 = 0.f, s3 = 0.f;
#pragma unroll
            for (int d4 = 0; d4 < 16; d4 += 4) {
                float4 ka = kr[d4 + 0];
                float4 kb = kr[d4 + 1];
                float4 kc = kr[d4 + 2];
                float4 kd = kr[d4 + 3];
                s0 += q[4*d4+ 0]*ka.x + q[4*d4+ 1]*ka.y + q[4*d4+ 2]*ka.z + q[4*d4+ 3]*ka.w;
                s1 += q[4*d4+ 4]*kb.x + q[4*d4+ 5]*kb.y + q[4*d4+ 6]*kb.z + q[4*d4+ 7]*kb.w;
                s2 += q[4*d4+ 8]*kc.x + q[4*d4+ 9]*kc.y + q[4*d4+10]*kc.z + q[4*d4+11]*kc.w;
                s3 += q[4*d4+12]*kd.x + q[4*d4+13]*kd.y + q[4*d4+14]*kd.z + q[4*d4+15]*kd.w;
            }
            const float sj = (s0 + s1) + (s2 + s3);
            const int jgj = k0 + j;
            int dd = qi - jgj; if (dd < 0) dd = -dd;
            const bool ok = (jgj < SS) && (dd <= w);
            Ss[t][j] = ok ? sj : -1e30f;
        }

        // per-thread online softmax update
        float tm = -1e30f;
#pragma unroll
        for (int j = 0; j < 32; j++) tm = fmaxf(tm, Ss[t][j]);
        const float mn = fmaxf(m, tm);
        const float c = __expf(m - mn);
        l *= c;
#pragma unroll
        for (int d = 0; d < 64; d++) o[d] *= c;

        for (int j = 0; j < 32; j++) {
            const float sv = Ss[t][j];
            const float p = (sv > -1e29f) ? __expf(sv - mn) : 0.f;
            l += p;
            const float4* vr = (const float4*)&Vs[j][0];
#pragma unroll
            for (int d4 = 0; d4 < 16; d4++) {
                float4 vv = vr[d4];
                o[4*d4+0] += p * vv.x; o[4*d4+1] += p * vv.y;
                o[4*d4+2] += p * vv.z; o[4*d4+3] += p * vv.w;
            }
        }
        m = mn;
    }

    const float inv = 1.f / l;
    float* op = ctx + ((size_t)(b * SS + qi)) * DD + h * DHH;
#pragma unroll
    for (int d4 = 0; d4 < 16; d4++) {
        float4 v;
        v.x = o[4*d4+0] * inv; v.y = o[4*d4+1] * inv;
        v.z = o[4*d4+2] * inv; v.w = o[4*d4+3] * inv;
        *(float4*)(op + 4 * d4) = v;
    }
}

// ---------------- LayerNorm (one block per row, D=512) ----------------------
__global__ __launch_bounds__(128)
void ln_kernel(const float* __restrict__ in, const float* __restrict__ g,
               const float* __restrict__ b, float* __restrict__ out)
{
    __shared__ float red[4];
    const int row = blockIdx.x;
    const int t = threadIdx.x;      // 128 threads, 4 floats each
    float4 v = ((const float4*)(in + (size_t)row * DD))[t];

    float s = v.x + v.y + v.z + v.w;
#pragma unroll
    for (int o1 = 16; o1; o1 >>= 1) s += __shfl_xor_sync(0xffffffffu, s, o1);
    if ((t & 31) == 0) red[t >> 5] = s;
    __syncthreads();
    const float mean = (red[0] + red[1] + red[2] + red[3]) * (1.f / 512.f);

    const float dx0 = v.x - mean, dx1 = v.y - mean, dx2 = v.z - mean, dx3 = v.w - mean;
    float sq = dx0*dx0 + dx1*dx1 + dx2*dx2 + dx3*dx3;
#pragma unroll
    for (int o1 = 16; o1; o1 >>= 1) sq += __shfl_xor_sync(0xffffffffu, sq, o1);
    __syncthreads();
    if ((t & 31) == 0) red[t >> 5] = sq;
    __syncthreads();
    const float var = (red[0] + red[1] + red[2] + red[3]) * (1.f / 512.f);
    const float rs = rsqrtf(var + 1e-5f);

    float4 gv = ((const float4*)g)[t];
    float4 bv = ((const float4*)b)[t];
    float4 ov;
    ov.x = dx0 * rs * gv.x + bv.x;
    ov.y = dx1 * rs * gv.y + bv.y;
    ov.z = dx2 * rs * gv.z + bv.z;
    ov.w = dx3 * rs * gv.w + bv.w;
    ((float4*)(out + (size_t)row * DD))[t] = ov;
}

// ---------------- launch ----------------------------------------------------
extern "C" void kernel_launch(void* const* d_in, const int* in_sizes, int n_in,
                              void* d_out, int out_size)
{
    const float* x     = (const float*)d_in[0];
    const float* w_in  = (const float*)d_in[1];
    const float* b_in  = (const float*)d_in[2];
    const float* w_out = (const float*)d_in[3];
    const float* b_out = (const float*)d_in[4];
    const float* ln1g  = (const float*)d_in[5];
    const float* ln1b  = (const float*)d_in[6];
    const float* ln2g  = (const float*)d_in[7];
    const float* ln2b  = (const float*)d_in[8];
    const float* w1    = (const float*)d_in[9];
    const float* b1    = (const float*)d_in[10];
    const float* w2    = (const float*)d_in[11];
    const float* b2    = (const float*)d_in[12];
    const int*   wnd   = (const int*)d_in[13];

    float *qkv, *ctx, *r1, *hbuf, *mid;
    cudaGetSymbolAddress((void**)&qkv,  g_qkv);
    cudaGetSymbolAddress((void**)&ctx,  g_ctx);
    cudaGetSymbolAddress((void**)&r1,   g_r1);
    cudaGetSymbolAddress((void**)&hbuf, g_h);
    cudaGetSymbolAddress((void**)&mid,  g_mid);

    // 1) fused QKV projection
    sgemm_nt<0><<<dim3(12, 64), 256>>>(x, w_in, b_in, nullptr, qkv, MM, 1536, DD);
    // 2) sliding-window attention
    attn_kernel<<<dim3(32, HH, BB), 128>>>(qkv, ctx, wnd);
    // 3) out_proj + residual(x)
    sgemm_nt<1><<<dim3(4, 64), 256>>>(ctx, w_out, b_out, x, r1, MM, DD, DD);
    // 4) LN1
    ln_kernel<<<MM, 128>>>(r1, ln1g, ln1b, hbuf);
    // 5) MLP fc1 + relu
    sgemm_nt<2><<<dim3(4, 64), 256>>>(hbuf, w1, b1, nullptr, mid, MM, DD, DD);
    // 6) MLP fc2 + residual(h)
    sgemm_nt<1><<<dim3(4, 64), 256>>>(mid, w2, b2, hbuf, r1, MM, DD, DD);
    // 7) LN2 -> output
    ln_kernel<<<MM, 128>>>(r1, ln2g, ln2b, (float*)d_out);
}

// round 4
// speedup vs baseline: 1.3867x; 1.3867x over previous
#include <cuda_runtime.h>
#include <cstdint>
#include <math.h>

// Problem constants (fixed shapes per reference)
#define BB   2
#define SS   4096
#define DD   512
#define HH   8
#define DHH  64
#define MM   (BB*SS)      // 8192 rows

// ---------------- scratch (device globals; no allocations allowed) ----------
__device__ float g_qkv[MM * 1536];
__device__ float g_ctx[MM * DD];
__device__ float g_r1 [MM * DD];
__device__ float g_h  [MM * DD];
__device__ float g_mid[MM * DD];

// ---------------- helpers ----------------------------------------------------
__device__ __forceinline__ float tf32r(float x) {
    float y; asm("cvt.rna.tf32.f32 %0, %1;" : "=f"(y) : "f"(x)); return y;
}

__device__ __forceinline__ void mma_tf32(float* d, const float* a, const float* b) {
    // m16n8k8 row.col tf32 -> f32, D = A*B + D
    asm volatile(
        "mma.sync.aligned.m16n8k8.row.col.f32.tf32.tf32.f32 "
        "{%0,%1,%2,%3}, {%4,%5,%6,%7}, {%8,%9}, {%0,%1,%2,%3};"
        : "+f"(d[0]), "+f"(d[1]), "+f"(d[2]), "+f"(d[3])
        : "r"(__float_as_uint(a[0])), "r"(__float_as_uint(a[1])),
          "r"(__float_as_uint(a[2])), "r"(__float_as_uint(a[3])),
          "r"(__float_as_uint(b[0])), "r"(__float_as_uint(b[1])));
}

// ================= tf32 mma.sync GEMM: C = A @ W^T + bias (+epilogue) =======
// A:[M,K] row-major, W:[N,K] row-major, C:[M,N]. K multiple of 8, tiles 128x128.
// MODE 0: +bias; MODE 1: +bias+resid; MODE 2: +bias+relu
template<int MODE>
__global__ __launch_bounds__(256)
void gemm_mma(const float* __restrict__ A, const float* __restrict__ W,
              const float* __restrict__ bias, const float* __restrict__ resid,
              float* __restrict__ C, int M, int N, int K)
{
    __shared__ float As[2][128][8];   // [stage][row][k] — stride 8 floats
    __shared__ float Ws[2][128][8];

    const int t    = threadIdx.x;
    const int warp = t >> 5;
    const int lane = t & 31;
    const int grp  = lane >> 2;       // 0..7
    const int tig  = lane & 3;        // 0..3
    const int wm   = (warp >> 1) * 32;  // warp m-offset (4 warps in m)
    const int wn   = (warp & 1) * 64;   // warp n-offset (2 warps in n)
    const int brow = blockIdx.y * 128;
    const int bcol = blockIdx.x * 128;

    const int lr  = t >> 1;           // 0..127 (staging row)
    const int lkc = (t & 1) * 4;      // 0 or 4 (staging k chunk)

    const float* Ap = A + (size_t)(brow + lr) * K + lkc;
    const float* Wp = W + (size_t)(bcol + lr) * K + lkc;

    float acc[2][8][4];
#pragma unroll
    for (int mt = 0; mt < 2; mt++)
#pragma unroll
        for (int nt = 0; nt < 8; nt++)
#pragma unroll
            for (int r = 0; r < 4; r++) acc[mt][nt][r] = 0.f;

    // prolog: stage 0
    {
        float4 av = *(const float4*)Ap;
        float4 wv = *(const float4*)Wp;
        float* as = &As[0][lr][lkc];
        as[0] = tf32r(av.x); as[1] = tf32r(av.y); as[2] = tf32r(av.z); as[3] = tf32r(av.w);
        float* ws = &Ws[0][lr][lkc];
        ws[0] = tf32r(wv.x); ws[1] = tf32r(wv.y); ws[2] = tf32r(wv.z); ws[3] = tf32r(wv.w);
    }
    __syncthreads();

    const int NS = K >> 3;
    for (int s = 0; s < NS; s++) {
        float4 av, wv;
        if (s + 1 < NS) {
            av = *(const float4*)(Ap + (s + 1) * 8);
            wv = *(const float4*)(Wp + (s + 1) * 8);
        }

        const int buf = s & 1;
        // A fragments (2 m-tiles)
        float afr[2][4];
#pragma unroll
        for (int mt = 0; mt < 2; mt++) {
            const int rb = wm + mt * 16;
            afr[mt][0] = As[buf][rb + grp    ][tig];
            afr[mt][1] = As[buf][rb + grp + 8][tig];
            afr[mt][2] = As[buf][rb + grp    ][tig + 4 - 4 + 4]; // tig+4
            afr[mt][3] = As[buf][rb + grp + 8][tig + 4];
        }
        // fix: the [tig+4] column index (k = tig+4)
        afr[0][2] = As[buf][wm + grp     ][tig + 4];
        afr[1][2] = As[buf][wm + 16 + grp][tig + 4];

        // B fragments (8 n-tiles)
        float bfr[8][2];
#pragma unroll
        for (int nt = 0; nt < 8; nt++) {
            const int nb = wn + nt * 8 + grp;
            bfr[nt][0] = Ws[buf][nb][tig];
            bfr[nt][1] = Ws[buf][nb][tig + 4];
        }

#pragma unroll
        for (int mt = 0; mt < 2; mt++)
#pragma unroll
            for (int nt = 0; nt < 8; nt++)
                mma_tf32(acc[mt][nt], afr[mt], bfr[nt]);

        if (s + 1 < NS) {
            const int nb = (s + 1) & 1;
            float* as = &As[nb][lr][lkc];
            as[0] = tf32r(av.x); as[1] = tf32r(av.y); as[2] = tf32r(av.z); as[3] = tf32r(av.w);
            float* ws = &Ws[nb][lr][lkc];
            ws[0] = tf32r(wv.x); ws[1] = tf32r(wv.y); ws[2] = tf32r(wv.z); ws[3] = tf32r(wv.w);
        }
        __syncthreads();
    }

    // epilogue: c fragment (mt,nt): rows wm+16mt+grp(+8), cols wn+8nt+2tig(+1)
#pragma unroll
    for (int mt = 0; mt < 2; mt++) {
#pragma unroll
        for (int half = 0; half < 2; half++) {
            const int grow = brow + wm + 16 * mt + grp + 8 * half;
            float* crow = C + (size_t)grow * N + bcol;
            const float* rrow = (MODE == 1) ? (resid + (size_t)grow * N + bcol) : nullptr;
#pragma unroll
            for (int nt = 0; nt < 8; nt++) {
                const int col = wn + 8 * nt + 2 * tig;
                float2 o;
                o.x = acc[mt][nt][2 * half + 0] + bias[bcol + col];
                o.y = acc[mt][nt][2 * half + 1] + bias[bcol + col + 1];
                if (MODE == 1) {
                    const float2 rv = *(const float2*)(rrow + col);
                    o.x += rv.x; o.y += rv.y;
                }
                if (MODE == 2) {
                    o.x = fmaxf(o.x, 0.f); o.y = fmaxf(o.y, 0.f);
                }
                *(float2*)(crow + col) = o;
            }
        }
    }
}

// ---------------- sliding-window attention (fp32 SIMT) -----------------------
__global__ __launch_bounds__(128)
void attn_kernel(const float* __restrict__ qkv, float* __restrict__ ctx,
                 const int* __restrict__ wptr)
{
    __shared__ float Ks[32][68];
    __shared__ float Vs[32][68];
    __shared__ float Ss[128][33];

    int w = *wptr;
    if (w < 0 || w > 1000000) w = (int)__int_as_float((unsigned)w);

    const int t  = threadIdx.x;
    const int qt = blockIdx.x;
    const int h  = blockIdx.y;
    const int b  = blockIdx.z;
    const int q0 = qt * 128;
    const int qi = q0 + t;
    const float scale = rsqrtf((float)DHH);

    float q[64], o[64];
    const float* qp = qkv + ((size_t)(b * SS + qi)) * 1536 + h * DHH;
#pragma unroll
    for (int d4 = 0; d4 < 16; d4++) {
        float4 v = *(const float4*)(qp + 4 * d4);
        q[4*d4+0] = v.x * scale; q[4*d4+1] = v.y * scale;
        q[4*d4+2] = v.z * scale; q[4*d4+3] = v.w * scale;
        o[4*d4+0] = 0.f; o[4*d4+1] = 0.f; o[4*d4+2] = 0.f; o[4*d4+3] = 0.f;
    }

    float m = -1e30f, l = 0.f;
    int kstart = q0 - w;       if (kstart < 0)  kstart = 0;
    int kend   = q0 + 128 + w; if (kend > SS)   kend = SS;

    const int jr = t >> 2;
    const int dc = (t & 3) << 4;

    for (int k0 = kstart; k0 < kend; k0 += 32) {
        __syncthreads();
        {
            const int jg = k0 + jr;
            if (jg < SS) {
                const float* kp = qkv + ((size_t)(b * SS + jg)) * 1536 + 512 + h * DHH + dc;
                const float* vp = kp + 512;
                float4 a0 = *(const float4*)(kp + 0);
                float4 a1 = *(const float4*)(kp + 4);
                float4 a2 = *(const float4*)(kp + 8);
                float4 a3 = *(const float4*)(kp + 12);
                *(float4*)&Ks[jr][dc + 0]  = a0;
                *(float4*)&Ks[jr][dc + 4]  = a1;
                *(float4*)&Ks[jr][dc + 8]  = a2;
                *(float4*)&Ks[jr][dc + 12] = a3;
                float4 c0 = *(const float4*)(vp + 0);
                float4 c1 = *(const float4*)(vp + 4);
                float4 c2 = *(const float4*)(vp + 8);
                float4 c3 = *(const float4*)(vp + 12);
                *(float4*)&Vs[jr][dc + 0]  = c0;
                *(float4*)&Vs[jr][dc + 4]  = c1;
                *(float4*)&Vs[jr][dc + 8]  = c2;
                *(float4*)&Vs[jr][dc + 12] = c3;
            } else {
                float4 z = make_float4(0.f, 0.f, 0.f, 0.f);
                *(float4*)&Ks[jr][dc + 0]  = z; *(float4*)&Ks[jr][dc + 4]  = z;
                *(float4*)&Ks[jr][dc + 8]  = z; *(float4*)&Ks[jr][dc + 12] = z;
                *(float4*)&Vs[jr][dc + 0]  = z; *(float4*)&Vs[jr][dc + 4]  = z;
                *(float4*)&Vs[jr][dc + 8]  = z; *(float4*)&Vs[jr][dc + 12] = z;
            }
        }
        __syncthreads();

        for (int j = 0; j < 32; j++) {
            const float4* kr = (const float4*)&Ks[j][0];
            float s0 = 0.f, s1 = 0.f, s2 = 0.f, s3 = 0.f;
#pragma unroll
            for (int d4 = 0; d4 < 16; d4 += 4) {
                float4 ka = kr[d4 + 0];
                float4 kb = kr[d4 + 1];
                float4 kc = kr[d4 + 2];
                float4 kd = kr[d4 + 3];
                s0 += q[4*d4+ 0]*ka.x + q[4*d4+ 1]*ka.y + q[4*d4+ 2]*ka.z + q[4*d4+ 3]*ka.w;
                s1 += q[4*d4+ 4]*kb.x + q[4*d4+ 5]*kb.y + q[4*d4+ 6]*kb.z + q[4*d4+ 7]*kb.w;
                s2 += q[4*d4+ 8]*kc.x + q[4*d4+ 9]*kc.y + q[4*d4+10]*kc.z + q[4*d4+11]*kc.w;
                s3 += q[4*d4+12]*kd.x + q[4*d4+13]*kd.y + q[4*d4+14]*kd.z + q[4*d4+15]*kd.w;
            }
            const float sj = (s0 + s1) + (s2 + s3);
            const int jgj = k0 + j;
            int dd = qi - jgj; if (dd < 0) dd = -dd;
            const bool ok = (jgj < SS) && (dd <= w);
            Ss[t][j] = ok ? sj : -1e30f;
        }

        float tm = -1e30f;
#pragma unroll
        for (int j = 0; j < 32; j++) tm = fmaxf(tm, Ss[t][j]);
        const float mn = fmaxf(m, tm);
        const float c = __expf(m - mn);
        l *= c;
#pragma unroll
        for (int d = 0; d < 64; d++) o[d] *= c;

        for (int j = 0; j < 32; j++) {
            const float sv = Ss[t][j];
            const float p = (sv > -1e29f) ? __expf(sv - mn) : 0.f;
            l += p;
            const float4* vr = (const float4*)&Vs[j][0];
#pragma unroll
            for (int d4 = 0; d4 < 16; d4++) {
                float4 vv = vr[d4];
                o[4*d4+0] += p * vv.x; o[4*d4+1] += p * vv.y;
                o[4*d4+2] += p * vv.z; o[4*d4+3] += p * vv.w;
            }
        }
        m = mn;
    }

    const float inv = 1.f / l;
    float* op = ctx + ((size_t)(b * SS + qi)) * DD + h * DHH;
#pragma unroll
    for (int d4 = 0; d4 < 16; d4++) {
        float4 v;
        v.x = o[4*d4+0] * inv; v.y = o[4*d4+1] * inv;
        v.z = o[4*d4+2] * inv; v.w = o[4*d4+3] * inv;
        *(float4*)(op + 4 * d4) = v;
    }
}

// ---------------- LayerNorm (one block per row, D=512) ----------------------
__global__ __launch_bounds__(128)
void ln_kernel(const float* __restrict__ in, const float* __restrict__ g,
               const float* __restrict__ b, float* __restrict__ out)
{
    __shared__ float red[4];
    const int row = blockIdx.x;
    const int t = threadIdx.x;
    float4 v = ((const float4*)(in + (size_t)row * DD))[t];

    float s = v.x + v.y + v.z + v.w;
#pragma unroll
    for (int o1 = 16; o1; o1 >>= 1) s += __shfl_xor_sync(0xffffffffu, s, o1);
    if ((t & 31) == 0) red[t >> 5] = s;
    __syncthreads();
    const float mean = (red[0] + red[1] + red[2] + red[3]) * (1.f / 512.f);

    const float dx0 = v.x - mean, dx1 = v.y - mean, dx2 = v.z - mean, dx3 = v.w - mean;
    float sq = dx0*dx0 + dx1*dx1 + dx2*dx2 + dx3*dx3;
#pragma unroll
    for (int o1 = 16; o1; o1 >>= 1) sq += __shfl_xor_sync(0xffffffffu, sq, o1);
    __syncthreads();
    if ((t & 31) == 0) red[t >> 5] = sq;
    __syncthreads();
    const float var = (red[0] + red[1] + red[2] + red[3]) * (1.f / 512.f);
    const float rs = rsqrtf(var + 1e-5f);

    float4 gv = ((const float4*)g)[t];
    float4 bv = ((const float4*)b)[t];
    float4 ov;
    ov.x = dx0 * rs * gv.x + bv.x;
    ov.y = dx1 * rs * gv.y + bv.y;
    ov.z = dx2 * rs * gv.z + bv.z;
    ov.w = dx3 * rs * gv.w + bv.w;
    ((float4*)(out + (size_t)row * DD))[t] = ov;
}

// ---------------- launch ----------------------------------------------------
extern "C" void kernel_launch(void* const* d_in, const int* in_sizes, int n_in,
                              void* d_out, int out_size)
{
    const float* x     = (const float*)d_in[0];
    const float* w_in  = (const float*)d_in[1];
    const float* b_in  = (const float*)d_in[2];
    const float* w_out = (const float*)d_in[3];
    const float* b_out = (const float*)d_in[4];
    const float* ln1g  = (const float*)d_in[5];
    const float* ln1b  = (const float*)d_in[6];
    const float* ln2g  = (const float*)d_in[7];
    const float* ln2b  = (const float*)d_in[8];
    const float* w1    = (const float*)d_in[9];
    const float* b1    = (const float*)d_in[10];
    const float* w2    = (const float*)d_in[11];
    const float* b2    = (const float*)d_in[12];
    const int*   wnd   = (const int*)d_in[13];

    float *qkv, *ctx, *r1, *hbuf, *mid;
    cudaGetSymbolAddress((void**)&qkv,  g_qkv);
    cudaGetSymbolAddress((void**)&ctx,  g_ctx);
    cudaGetSymbolAddress((void**)&r1,   g_r1);
    cudaGetSymbolAddress((void**)&hbuf, g_h);
    cudaGetSymbolAddress((void**)&mid,  g_mid);

    // 1) fused QKV projection (tf32 mma.sync)
    gemm_mma<0><<<dim3(12, 64), 256>>>(x, w_in, b_in, nullptr, qkv, MM, 1536, DD);
    // 2) sliding-window attention
    attn_kernel<<<dim3(32, HH, BB), 128>>>(qkv, ctx, wnd);
    // 3) out_proj + residual(x)
    gemm_mma<1><<<dim3(4, 64), 256>>>(ctx, w_out, b_out, x, r1, MM, DD, DD);
    // 4) LN1
    ln_kernel<<<MM, 128>>>(r1, ln1g, ln1b, hbuf);
    // 5) MLP fc1 + relu
    gemm_mma<2><<<dim3(4, 64), 256>>>(hbuf, w1, b1, nullptr, mid, MM, DD, DD);
    // 6) MLP fc2 + residual(h)
    gemm_mma<1><<<dim3(4, 64), 256>>>(mid, w2, b2, hbuf, r1, MM, DD, DD);
    // 7) LN2 -> output
    ln_kernel<<<MM, 128>>>(r1, ln2g, ln2b, (float*)d_out);
}

// round 5
// speedup vs baseline: 2.2280x; 1.6066x over previous
#include <cuda_runtime.h>
#include <cstdint>
#include <math.h>

// Problem constants (fixed shapes per reference)
#define BB   2
#define SS   4096
#define DD   512
#define HH   8
#define DHH  64
#define MM   (BB*SS)      // 8192 rows

// ---------------- scratch (device globals; no allocations allowed) ----------
__device__ float g_qkv[MM * 1536];
__device__ float g_ctx[MM * DD];
__device__ float g_r1 [MM * DD];
__device__ float g_h  [MM * DD];
__device__ float g_mid[MM * DD];

// ---------------- helpers ----------------------------------------------------
__device__ __forceinline__ float tf32r(float x) {
    float y; asm("cvt.rna.tf32.f32 %0, %1;" : "=f"(y) : "f"(x)); return y;
}

__device__ __forceinline__ void mma_tf32(float* d, const float* a, const float* b) {
    // m16n8k8 row.col tf32 -> f32, D = A*B + D
    asm volatile(
        "mma.sync.aligned.m16n8k8.row.col.f32.tf32.tf32.f32 "
        "{%0,%1,%2,%3}, {%4,%5,%6,%7}, {%8,%9}, {%0,%1,%2,%3};"
        : "+f"(d[0]), "+f"(d[1]), "+f"(d[2]), "+f"(d[3])
        : "r"(__float_as_uint(a[0])), "r"(__float_as_uint(a[1])),
          "r"(__float_as_uint(a[2])), "r"(__float_as_uint(a[3])),
          "r"(__float_as_uint(b[0])), "r"(__float_as_uint(b[1])));
}

// ================= tf32 mma.sync GEMM: C = A @ W^T + bias (+epilogue) =======
// A:[M,K] row-major, W:[N,K] row-major, C:[M,N]. K multiple of 16, tile 128x128.
// BK=16, smem stride 20 floats -> conflict-free fragment loads.
// MODE 0: +bias; MODE 1: +bias+resid; MODE 2: +bias+relu
template<int MODE>
__global__ __launch_bounds__(256)
void gemm_mma(const float* __restrict__ A, const float* __restrict__ W,
              const float* __restrict__ bias, const float* __restrict__ resid,
              float* __restrict__ C, int M, int N, int K)
{
    __shared__ float As[2][128][20];   // [stage][row][k] stride 20 (16 used)
    __shared__ float Ws[2][128][20];

    const int t    = threadIdx.x;
    const int warp = t >> 5;
    const int lane = t & 31;
    const int grp  = lane >> 2;       // 0..7
    const int tig  = lane & 3;        // 0..3
    const int wm   = (warp >> 1) * 32;  // 4 warps in m
    const int wn   = (warp & 1) * 64;   // 2 warps in n
    const int brow = blockIdx.y * 128;
    const int bcol = blockIdx.x * 128;

    const int lr  = t >> 1;           // staging row 0..127
    const int lkc = (t & 1) * 8;      // staging k chunk 0 or 8

    const float* Ap = A + (size_t)(brow + lr) * K + lkc;
    const float* Wp = W + (size_t)(bcol + lr) * K + lkc;

    float acc[2][8][4];
#pragma unroll
    for (int mt = 0; mt < 2; mt++)
#pragma unroll
        for (int nt = 0; nt < 8; nt++)
#pragma unroll
            for (int r = 0; r < 4; r++) acc[mt][nt][r] = 0.f;

    // prolog: stage 0
    {
        float4 a0 = *(const float4*)(Ap);
        float4 a1 = *(const float4*)(Ap + 4);
        float4 w0 = *(const float4*)(Wp);
        float4 w1 = *(const float4*)(Wp + 4);
        float* as = &As[0][lr][lkc];
        as[0]=tf32r(a0.x); as[1]=tf32r(a0.y); as[2]=tf32r(a0.z); as[3]=tf32r(a0.w);
        as[4]=tf32r(a1.x); as[5]=tf32r(a1.y); as[6]=tf32r(a1.z); as[7]=tf32r(a1.w);
        float* ws = &Ws[0][lr][lkc];
        ws[0]=tf32r(w0.x); ws[1]=tf32r(w0.y); ws[2]=tf32r(w0.z); ws[3]=tf32r(w0.w);
        ws[4]=tf32r(w1.x); ws[5]=tf32r(w1.y); ws[6]=tf32r(w1.z); ws[7]=tf32r(w1.w);
    }
    __syncthreads();

    const int NS = K >> 4;   // K/16 stages
    for (int s = 0; s < NS; s++) {
        float4 a0, a1, w0, w1;
        if (s + 1 < NS) {
            a0 = *(const float4*)(Ap + (s + 1) * 16);
            a1 = *(const float4*)(Ap + (s + 1) * 16 + 4);
            w0 = *(const float4*)(Wp + (s + 1) * 16);
            w1 = *(const float4*)(Wp + (s + 1) * 16 + 4);
        }

        const int buf = s & 1;
#pragma unroll
        for (int ks = 0; ks < 2; ks++) {
            const int ko = 8 * ks;
            float afr[2][4];
#pragma unroll
            for (int mt = 0; mt < 2; mt++) {
                const int rb = wm + mt * 16;
                afr[mt][0] = As[buf][rb + grp    ][ko + tig];
                afr[mt][1] = As[buf][rb + grp + 8][ko + tig];
                afr[mt][2] = As[buf][rb + grp    ][ko + tig + 4];
                afr[mt][3] = As[buf][rb + grp + 8][ko + tig + 4];
            }
            float bfr[8][2];
#pragma unroll
            for (int nt = 0; nt < 8; nt++) {
                const int nb = wn + nt * 8 + grp;
                bfr[nt][0] = Ws[buf][nb][ko + tig];
                bfr[nt][1] = Ws[buf][nb][ko + tig + 4];
            }
#pragma unroll
            for (int mt = 0; mt < 2; mt++)
#pragma unroll
                for (int nt = 0; nt < 8; nt++)
                    mma_tf32(acc[mt][nt], afr[mt], bfr[nt]);
        }

        if (s + 1 < NS) {
            const int nb = (s + 1) & 1;
            float* as = &As[nb][lr][lkc];
            as[0]=tf32r(a0.x); as[1]=tf32r(a0.y); as[2]=tf32r(a0.z); as[3]=tf32r(a0.w);
            as[4]=tf32r(a1.x); as[5]=tf32r(a1.y); as[6]=tf32r(a1.z); as[7]=tf32r(a1.w);
            float* ws = &Ws[nb][lr][lkc];
            ws[0]=tf32r(w0.x); ws[1]=tf32r(w0.y); ws[2]=tf32r(w0.z); ws[3]=tf32r(w0.w);
            ws[4]=tf32r(w1.x); ws[5]=tf32r(w1.y); ws[6]=tf32r(w1.z); ws[7]=tf32r(w1.w);
        }
        __syncthreads();
    }

    // epilogue: c fragment (mt,nt): rows wm+16mt+grp(+8), cols wn+8nt+2tig(+1)
#pragma unroll
    for (int mt = 0; mt < 2; mt++) {
#pragma unroll
        for (int half = 0; half < 2; half++) {
            const int grow = brow + wm + 16 * mt + grp + 8 * half;
            float* crow = C + (size_t)grow * N + bcol;
            const float* rrow = (MODE == 1) ? (resid + (size_t)grow * N + bcol) : nullptr;
#pragma unroll
            for (int nt = 0; nt < 8; nt++) {
                const int col = wn + 8 * nt + 2 * tig;
                float2 o;
                o.x = acc[mt][nt][2 * half + 0] + bias[bcol + col];
                o.y = acc[mt][nt][2 * half + 1] + bias[bcol + col + 1];
                if (MODE == 1) {
                    const float2 rv = *(const float2*)(rrow + col);
                    o.x += rv.x; o.y += rv.y;
                }
                if (MODE == 2) {
                    o.x = fmaxf(o.x, 0.f); o.y = fmaxf(o.y, 0.f);
                }
                *(float2*)(crow + col) = o;
            }
        }
    }
}

// ============ sliding-window flash attention with tf32 mma ===================
// Q tile 64 rows, 4 warps (16 rows/warp). Q frags in registers.
// K/P smem stride 68 (4*grp+tig banks, conflict-free), V stride 76 (12*tig+grp).
#define KS_STR 68
#define VS_STR 76
#define PS_STR 68
#define OFF_V  (64*KS_STR)
#define OFF_P  (OFF_V + 64*VS_STR)
#define ATT_SMEM ((OFF_P + 64*PS_STR) * 4)    // 54272 bytes

__global__ __launch_bounds__(128)
void attn_mma(const float* __restrict__ qkv, float* __restrict__ ctx,
              const int* __restrict__ wptr)
{
    extern __shared__ float sm[];
    float* Ks = sm;
    float* Vs = sm + OFF_V;
    float* Ps = sm + OFF_P;

    int w = *wptr;
    if (w < 0 || w > 1000000) w = (int)__int_as_float((unsigned)w);

    const int t    = threadIdx.x;
    const int warp = t >> 5;
    const int lane = t & 31;
    const int grp  = lane >> 2;
    const int tig  = lane & 3;
    const int wm   = warp * 16;
    const int q0   = blockIdx.x * 64;
    const int h    = blockIdx.y;
    const int b    = blockIdx.z;

    // ---- stage Q into Ks (raw), build register A-frags (scaled, tf32) ------
    {
        const int r = t >> 1, c0 = (t & 1) * 32;
        const float* qp = qkv + ((size_t)(b * SS + q0 + r)) * 1536 + h * 64 + c0;
#pragma unroll
        for (int i = 0; i < 8; i++)
            *(float4*)&Ks[r * KS_STR + c0 + 4 * i] = *(const float4*)(qp + 4 * i);
    }
    __syncthreads();
    const int r0 = wm + grp, r1 = r0 + 8;
    float aq[8][4];
#pragma unroll
    for (int s = 0; s < 8; s++) {
        aq[s][0] = tf32r(Ks[r0 * KS_STR + 8 * s + tig    ] * 0.125f);
        aq[s][1] = tf32r(Ks[r1 * KS_STR + 8 * s + tig    ] * 0.125f);
        aq[s][2] = tf32r(Ks[r0 * KS_STR + 8 * s + tig + 4] * 0.125f);
        aq[s][3] = tf32r(Ks[r1 * KS_STR + 8 * s + tig + 4] * 0.125f);
    }

    float oc[8][4];
#pragma unroll
    for (int nt = 0; nt < 8; nt++) { oc[nt][0]=0.f; oc[nt][1]=0.f; oc[nt][2]=0.f; oc[nt][3]=0.f; }
    float m0 = -1e30f, m1 = -1e30f, l0 = 0.f, l1 = 0.f;
    const int qg0 = q0 + wm + grp, qg1 = qg0 + 8;

    int j0s = q0 - w; if (j0s < 0) j0s = 0; j0s &= ~63;
    int jend = q0 + 64 + w; if (jend > SS) jend = SS;

    for (int j0 = j0s; j0 < jend; j0 += 64) {
        __syncthreads();   // all warps done reading Ks/Vs (or Q frags, 1st iter)
        {
            const int r = t >> 1, c0 = (t & 1) * 32;
            const int jr = j0 + r;
            float* kd = &Ks[r * KS_STR + c0];
            float* vd = &Vs[r * VS_STR + c0];
            if (jr < SS) {
                const float* kp = qkv + ((size_t)(b * SS + jr)) * 1536 + 512 + h * 64 + c0;
                const float* vp = kp + 512;
#pragma unroll
                for (int i = 0; i < 8; i++) {
                    float4 kv = *(const float4*)(kp + 4 * i);
                    float4 vv = *(const float4*)(vp + 4 * i);
                    kv.x = tf32r(kv.x); kv.y = tf32r(kv.y); kv.z = tf32r(kv.z); kv.w = tf32r(kv.w);
                    vv.x = tf32r(vv.x); vv.y = tf32r(vv.y); vv.z = tf32r(vv.z); vv.w = tf32r(vv.w);
                    *(float4*)(kd + 4 * i) = kv;
                    *(float4*)(vd + 4 * i) = vv;
                }
            } else {
                const float4 z = make_float4(0.f, 0.f, 0.f, 0.f);
#pragma unroll
                for (int i = 0; i < 8; i++) { *(float4*)(kd + 4*i) = z; *(float4*)(vd + 4*i) = z; }
            }
        }
        __syncthreads();

        // ---- S = Q @ K^T --------------------------------------------------
        float sc[8][4];
#pragma unroll
        for (int nt = 0; nt < 8; nt++) { sc[nt][0]=0.f; sc[nt][1]=0.f; sc[nt][2]=0.f; sc[nt][3]=0.f; }
#pragma unroll
        for (int s = 0; s < 8; s++) {
#pragma unroll
            for (int nt = 0; nt < 8; nt++) {
                float bb[2];
                bb[0] = Ks[(8 * nt + grp) * KS_STR + 8 * s + tig];
                bb[1] = Ks[(8 * nt + grp) * KS_STR + 8 * s + tig + 4];
                mma_tf32(sc[nt], aq[s], bb);
            }
        }

        // ---- mask + online softmax ---------------------------------------
        float tm0 = -1e30f, tm1 = -1e30f;
#pragma unroll
        for (int nt = 0; nt < 8; nt++) {
            const int ja = j0 + 8 * nt + 2 * tig;
            const int jb = ja + 1;
            if (ja >= SS || abs(qg0 - ja) > w) sc[nt][0] = -1e30f;
            if (jb >= SS || abs(qg0 - jb) > w) sc[nt][1] = -1e30f;
            if (ja >= SS || abs(qg1 - ja) > w) sc[nt][2] = -1e30f;
            if (jb >= SS || abs(qg1 - jb) > w) sc[nt][3] = -1e30f;
            tm0 = fmaxf(tm0, fmaxf(sc[nt][0], sc[nt][1]));
            tm1 = fmaxf(tm1, fmaxf(sc[nt][2], sc[nt][3]));
        }
        tm0 = fmaxf(tm0, __shfl_xor_sync(0xffffffffu, tm0, 1));
        tm0 = fmaxf(tm0, __shfl_xor_sync(0xffffffffu, tm0, 2));
        tm1 = fmaxf(tm1, __shfl_xor_sync(0xffffffffu, tm1, 1));
        tm1 = fmaxf(tm1, __shfl_xor_sync(0xffffffffu, tm1, 2));
        const float mn0 = fmaxf(m0, tm0), mn1 = fmaxf(m1, tm1);
        const float cf0 = __expf(m0 - mn0), cf1 = __expf(m1 - mn1);
        l0 *= cf0; l1 *= cf1;
#pragma unroll
        for (int nt = 0; nt < 8; nt++) {
            oc[nt][0] *= cf0; oc[nt][1] *= cf0;
            oc[nt][2] *= cf1; oc[nt][3] *= cf1;
        }
        float rs0 = 0.f, rs1 = 0.f;
#pragma unroll
        for (int nt = 0; nt < 8; nt++) {
            const float p00 = __expf(sc[nt][0] - mn0);
            const float p01 = __expf(sc[nt][1] - mn0);
            const float p10 = __expf(sc[nt][2] - mn1);
            const float p11 = __expf(sc[nt][3] - mn1);
            rs0 += p00 + p01; rs1 += p10 + p11;
            float2 w0; w0.x = tf32r(p00); w0.y = tf32r(p01);
            float2 w1; w1.x = tf32r(p10); w1.y = tf32r(p11);
            *(float2*)&Ps[r0 * PS_STR + 8 * nt + 2 * tig] = w0;
            *(float2*)&Ps[r1 * PS_STR + 8 * nt + 2 * tig] = w1;
        }
        rs0 += __shfl_xor_sync(0xffffffffu, rs0, 1);
        rs0 += __shfl_xor_sync(0xffffffffu, rs0, 2);
        rs1 += __shfl_xor_sync(0xffffffffu, rs1, 1);
        rs1 += __shfl_xor_sync(0xffffffffu, rs1, 2);
        l0 += rs0; l1 += rs1;
        m0 = mn0; m1 = mn1;
        __syncwarp();   // P rows are warp-private: only warp-level ordering needed

        // ---- O += P @ V ---------------------------------------------------
#pragma unroll
        for (int s = 0; s < 8; s++) {
            float ap[4];
            ap[0] = Ps[r0 * PS_STR + 8 * s + tig];
            ap[1] = Ps[r1 * PS_STR + 8 * s + tig];
            ap[2] = Ps[r0 * PS_STR + 8 * s + tig + 4];
            ap[3] = Ps[r1 * PS_STR + 8 * s + tig + 4];
#pragma unroll
            for (int nt = 0; nt < 8; nt++) {
                float bb[2];
                bb[0] = Vs[(8 * s + tig    ) * VS_STR + 8 * nt + grp];
                bb[1] = Vs[(8 * s + tig + 4) * VS_STR + 8 * nt + grp];
                mma_tf32(oc[nt], ap, bb);
            }
        }
    }

    const float inv0 = 1.f / l0, inv1 = 1.f / l1;
    float* o0 = ctx + ((size_t)(b * SS + qg0)) * DD + h * 64;
    float* o1 = ctx + ((size_t)(b * SS + qg1)) * DD + h * 64;
#pragma unroll
    for (int nt = 0; nt < 8; nt++) {
        const int d = 8 * nt + 2 * tig;
        float2 a; a.x = oc[nt][0] * inv0; a.y = oc[nt][1] * inv0;
        float2 c; c.x = oc[nt][2] * inv1; c.y = oc[nt][3] * inv1;
        *(float2*)(o0 + d) = a;
        *(float2*)(o1 + d) = c;
    }
}

// ---------------- LayerNorm (one block per row, D=512) ----------------------
__global__ __launch_bounds__(128)
void ln_kernel(const float* __restrict__ in, const float* __restrict__ g,
               const float* __restrict__ b, float* __restrict__ out)
{
    __shared__ float red[4];
    const int row = blockIdx.x;
    const int t = threadIdx.x;
    float4 v = ((const float4*)(in + (size_t)row * DD))[t];

    float s = v.x + v.y + v.z + v.w;
#pragma unroll
    for (int o1 = 16; o1; o1 >>= 1) s += __shfl_xor_sync(0xffffffffu, s, o1);
    if ((t & 31) == 0) red[t >> 5] = s;
    __syncthreads();
    const float mean = (red[0] + red[1] + red[2] + red[3]) * (1.f / 512.f);

    const float dx0 = v.x - mean, dx1 = v.y - mean, dx2 = v.z - mean, dx3 = v.w - mean;
    float sq = dx0*dx0 + dx1*dx1 + dx2*dx2 + dx3*dx3;
#pragma unroll
    for (int o1 = 16; o1; o1 >>= 1) sq += __shfl_xor_sync(0xffffffffu, sq, o1);
    __syncthreads();
    if ((t & 31) == 0) red[t >> 5] = sq;
    __syncthreads();
    const float var = (red[0] + red[1] + red[2] + red[3]) * (1.f / 512.f);
    const float rs = rsqrtf(var + 1e-5f);

    float4 gv = ((const float4*)g)[t];
    float4 bv = ((const float4*)b)[t];
    float4 ov;
    ov.x = dx0 * rs * gv.x + bv.x;
    ov.y = dx1 * rs * gv.y + bv.y;
    ov.z = dx2 * rs * gv.z + bv.z;
    ov.w = dx3 * rs * gv.w + bv.w;
    ((float4*)(out + (size_t)row * DD))[t] = ov;
}

// ---------------- launch ----------------------------------------------------
extern "C" void kernel_launch(void* const* d_in, const int* in_sizes, int n_in,
                              void* d_out, int out_size)
{
    const float* x     = (const float*)d_in[0];
    const float* w_in  = (const float*)d_in[1];
    const float* b_in  = (const float*)d_in[2];
    const float* w_out = (const float*)d_in[3];
    const float* b_out = (const float*)d_in[4];
    const float* ln1g  = (const float*)d_in[5];
    const float* ln1b  = (const float*)d_in[6];
    const float* ln2g  = (const float*)d_in[7];
    const float* ln2b  = (const float*)d_in[8];
    const float* w1    = (const float*)d_in[9];
    const float* b1    = (const float*)d_in[10];
    const float* w2    = (const float*)d_in[11];
    const float* b2    = (const float*)d_in[12];
    const int*   wnd   = (const int*)d_in[13];

    float *qkv, *ctx, *r1, *hbuf, *mid;
    cudaGetSymbolAddress((void**)&qkv,  g_qkv);
    cudaGetSymbolAddress((void**)&ctx,  g_ctx);
    cudaGetSymbolAddress((void**)&r1,   g_r1);
    cudaGetSymbolAddress((void**)&hbuf, g_h);
    cudaGetSymbolAddress((void**)&mid,  g_mid);

    cudaFuncSetAttribute(attn_mma, cudaFuncAttributeMaxDynamicSharedMemorySize, ATT_SMEM);

    // 1) fused QKV projection (tf32 mma.sync)
    gemm_mma<0><<<dim3(12, 64), 256>>>(x, w_in, b_in, nullptr, qkv, MM, 1536, DD);
    // 2) sliding-window flash attention (tf32 mma.sync)
    attn_mma<<<dim3(SS / 64, HH, BB), 128, ATT_SMEM>>>(qkv, ctx, wnd);
    // 3) out_proj + residual(x)
    gemm_mma<1><<<dim3(4, 64), 256>>>(ctx, w_out, b_out, x, r1, MM, DD, DD);
    // 4) LN1
    ln_kernel<<<MM, 128>>>(r1, ln1g, ln1b, hbuf);
    // 5) MLP fc1 + relu
    gemm_mma<2><<<dim3(4, 64), 256>>>(hbuf, w1, b1, nullptr, mid, MM, DD, DD);
    // 6) MLP fc2 + residual(h)
    gemm_mma<1><<<dim3(4, 64), 256>>>(mid, w2, b2, hbuf, r1, MM, DD, DD);
    // 7) LN2 -> output
    ln_kernel<<<MM, 128>>>(r1, ln2g, ln2b, (float*)d_out);
}

// round 6
// speedup vs baseline: 2.3605x; 1.0595x over previous
#include <cuda_runtime.h>
#include <cstdint>
#include <math.h>

// Problem constants (fixed shapes per reference)
#define BB   2
#define SS   4096
#define DD   512
#define HH   8
#define DHH  64
#define MM   (BB*SS)      // 8192 rows

// ---------------- scratch (device globals; no allocations allowed) ----------
__device__ float g_qkv[MM * 1536];
__device__ float g_ctx[MM * DD];
__device__ float g_r1 [MM * DD];
__device__ float g_h  [MM * DD];
__device__ float g_mid[MM * DD];

// ---------------- helpers ----------------------------------------------------
__device__ __forceinline__ float tf32r(float x) {
    float y; asm("cvt.rna.tf32.f32 %0, %1;" : "=f"(y) : "f"(x)); return y;
}

__device__ __forceinline__ void mma_tf32(float* d, const float* a, const float* b) {
    asm volatile(
        "mma.sync.aligned.m16n8k8.row.col.f32.tf32.tf32.f32 "
        "{%0,%1,%2,%3}, {%4,%5,%6,%7}, {%8,%9}, {%0,%1,%2,%3};"
        : "+f"(d[0]), "+f"(d[1]), "+f"(d[2]), "+f"(d[3])
        : "r"(__float_as_uint(a[0])), "r"(__float_as_uint(a[1])),
          "r"(__float_as_uint(a[2])), "r"(__float_as_uint(a[3])),
          "r"(__float_as_uint(b[0])), "r"(__float_as_uint(b[1])));
}

__device__ __forceinline__ void cpa16(uint32_t d, const void* s) {
    asm volatile("cp.async.ca.shared.global [%0], [%1], 16;" :: "r"(d), "l"(s));
}
__device__ __forceinline__ void cpa16z(uint32_t d, const void* s, int sz) {
    asm volatile("cp.async.ca.shared.global [%0], [%1], 16, %2;" :: "r"(d), "l"(s), "r"(sz));
}
__device__ __forceinline__ void cpa_commit() {
    asm volatile("cp.async.commit_group;" ::: "memory");
}
__device__ __forceinline__ void cpa_wait1() {
    asm volatile("cp.async.wait_group 1;" ::: "memory");
}
__device__ __forceinline__ void cpa_wait0() {
    asm volatile("cp.async.wait_group 0;" ::: "memory");
}

// ================= tf32 mma.sync GEMM (cp.async 3-stage) =====================
// C = A @ W^T + bias (+epilogue). A:[M,K], W:[N,K] row-major. K mult of 16.
// Tile 128x128, BK=16, smem stride 20 floats (conflict-free fragments).
// MODE 0: +bias; MODE 1: +bias+resid; MODE 2: +bias+relu
#define GSLOT (128*20)
#define GEMM_SMEM (3 * GSLOT * 2 * 4)     // 61440 bytes

template<int MODE>
__global__ __launch_bounds__(256)
void gemm_mma(const float* __restrict__ A, const float* __restrict__ W,
              const float* __restrict__ bias, const float* __restrict__ resid,
              float* __restrict__ C, int M, int N, int K)
{
    extern __shared__ float gsm[];
    float* As = gsm;                 // [3][128][20]
    float* Ws = gsm + 3 * GSLOT;

    const int t    = threadIdx.x;
    const int warp = t >> 5;
    const int lane = t & 31;
    const int grp  = lane >> 2;
    const int tig  = lane & 3;
    const int wm   = (warp >> 1) * 32;
    const int wn   = (warp & 1) * 64;
    const int brow = blockIdx.y * 128;
    const int bcol = blockIdx.x * 128;

    const int lr  = t >> 1;
    const int lkc = (t & 1) * 8;
    const float* ApG = A + (size_t)(brow + lr) * K + lkc;
    const float* WpG = W + (size_t)(bcol + lr) * K + lkc;
    const uint32_t sA = (uint32_t)__cvta_generic_to_shared(As + lr * 20 + lkc);
    const uint32_t sW = (uint32_t)__cvta_generic_to_shared(Ws + lr * 20 + lkc);

    const int NS = K >> 4;

#define GPREF(s) do { \
        const int _sl = (s) % 3; \
        const uint32_t _da = sA + _sl * (GSLOT * 4); \
        const uint32_t _dw = sW + _sl * (GSLOT * 4); \
        const float* _ga = ApG + (s) * 16; \
        const float* _gw = WpG + (s) * 16; \
        cpa16(_da,      _ga); \
        cpa16(_da + 16, _ga + 4); \
        cpa16(_dw,      _gw); \
        cpa16(_dw + 16, _gw + 4); \
        cpa_commit(); \
    } while (0)

    GPREF(0);
    GPREF(1);

    float acc[2][8][4];
#pragma unroll
    for (int mt = 0; mt < 2; mt++)
#pragma unroll
        for (int nt = 0; nt < 8; nt++)
#pragma unroll
            for (int r = 0; r < 4; r++) acc[mt][nt][r] = 0.f;

    for (int s = 0; s < NS; s++) {
        if (s == NS - 1) cpa_wait0(); else cpa_wait1();
        __syncthreads();
        if (s + 2 < NS) GPREF(s + 2);

        const float* Ab = As + (s % 3) * GSLOT;
        const float* Wb = Ws + (s % 3) * GSLOT;
#pragma unroll
        for (int ks = 0; ks < 2; ks++) {
            const int ko = 8 * ks;
            float afr[2][4];
#pragma unroll
            for (int mt = 0; mt < 2; mt++) {
                const int rb = wm + mt * 16;
                afr[mt][0] = tf32r(Ab[(rb + grp    ) * 20 + ko + tig    ]);
                afr[mt][1] = tf32r(Ab[(rb + grp + 8) * 20 + ko + tig    ]);
                afr[mt][2] = tf32r(Ab[(rb + grp    ) * 20 + ko + tig + 4]);
                afr[mt][3] = tf32r(Ab[(rb + grp + 8) * 20 + ko + tig + 4]);
            }
            float bfr[8][2];
#pragma unroll
            for (int nt = 0; nt < 8; nt++) {
                const int nb = wn + nt * 8 + grp;
                bfr[nt][0] = tf32r(Wb[nb * 20 + ko + tig    ]);
                bfr[nt][1] = tf32r(Wb[nb * 20 + ko + tig + 4]);
            }
#pragma unroll
            for (int mt = 0; mt < 2; mt++)
#pragma unroll
                for (int nt = 0; nt < 8; nt++)
                    mma_tf32(acc[mt][nt], afr[mt], bfr[nt]);
        }
    }

    // epilogue
#pragma unroll
    for (int mt = 0; mt < 2; mt++) {
#pragma unroll
        for (int half = 0; half < 2; half++) {
            const int grow = brow + wm + 16 * mt + grp + 8 * half;
            float* crow = C + (size_t)grow * N + bcol;
            const float* rrow = (MODE == 1) ? (resid + (size_t)grow * N + bcol) : nullptr;
#pragma unroll
            for (int nt = 0; nt < 8; nt++) {
                const int col = wn + 8 * nt + 2 * tig;
                float2 o;
                o.x = acc[mt][nt][2 * half + 0] + bias[bcol + col];
                o.y = acc[mt][nt][2 * half + 1] + bias[bcol + col + 1];
                if (MODE == 1) {
                    const float2 rv = *(const float2*)(rrow + col);
                    o.x += rv.x; o.y += rv.y;
                }
                if (MODE == 2) {
                    o.x = fmaxf(o.x, 0.f); o.y = fmaxf(o.y, 0.f);
                }
                *(float2*)(crow + col) = o;
            }
        }
    }
}

// ============ sliding-window flash attention, tf32 mma + cp.async ============
// Q tile 64 rows, 4 warps. K/V double-buffered via cp.async; Q staged via Ps.
#define KS_STR 68
#define VS_STR 76
#define PS_STR 68
#define OFF_V  (2*64*KS_STR)
#define OFF_P  (OFF_V + 2*64*VS_STR)
#define ATT_SMEM ((OFF_P + 64*PS_STR) * 4)    // 91136 bytes

__global__ __launch_bounds__(128)
void attn_mma(const float* __restrict__ qkv, float* __restrict__ ctx,
              const int* __restrict__ wptr)
{
    extern __shared__ float sm[];
    float* Ps = sm + OFF_P;

    int w = *wptr;
    if (w < 0 || w > 1000000) w = (int)__int_as_float((unsigned)w);

    const int t    = threadIdx.x;
    const int warp = t >> 5;
    const int lane = t & 31;
    const int grp  = lane >> 2;
    const int tig  = lane & 3;
    const int wm   = warp * 16;
    const int q0   = blockIdx.x * 64;
    const int h    = blockIdx.y;
    const int b    = blockIdx.z;

    const uint32_t smb = (uint32_t)__cvta_generic_to_shared(sm);

    int j0s = q0 - w; if (j0s < 0) j0s = 0; j0s &= ~63;
    int jend = q0 + 64 + w; if (jend > SS) jend = SS;
    const int ntl = (jend - j0s + 63) >> 6;

    // prefetch K/V tile: t<64 -> K row (t), t>=64 -> V row (t-64)
    const int pr  = t & 63;
    const int isV = t >> 6;
#define APREF(ti, buf) do { \
        const int _jr = j0s + (ti) * 64 + pr; \
        const int _sz = (_jr < SS) ? 16 : 0; \
        const int _jc = (_jr < SS) ? _jr : (SS - 1); \
        const float* _src = qkv + ((size_t)(b * SS + _jc)) * 1536 + 512 + isV * 512 + h * 64; \
        const uint32_t _dst = smb + 4u * (isV ? (OFF_V + (buf) * 64 * VS_STR + pr * VS_STR) \
                                              : ((buf) * 64 * KS_STR + pr * KS_STR)); \
        _Pragma("unroll") \
        for (int _ci = 0; _ci < 16; _ci++) cpa16z(_dst + 16 * _ci, _src + 4 * _ci, _sz); \
        cpa_commit(); \
    } while (0)

    // stage Q into Ps (free region), start K/V tile-0 prefetch
    {
        const int r = t >> 1, c0 = (t & 1) * 32;
        const float* qp = qkv + ((size_t)(b * SS + q0 + r)) * 1536 + h * 64 + c0;
#pragma unroll
        for (int i = 0; i < 8; i++)
            *(float4*)&Ps[r * PS_STR + c0 + 4 * i] = *(const float4*)(qp + 4 * i);
    }
    APREF(0, 0);
    __syncthreads();

    const int r0 = wm + grp, r1 = r0 + 8;
    float aq[8][4];
#pragma unroll
    for (int s = 0; s < 8; s++) {
        aq[s][0] = tf32r(Ps[r0 * PS_STR + 8 * s + tig    ] * 0.125f);
        aq[s][1] = tf32r(Ps[r1 * PS_STR + 8 * s + tig    ] * 0.125f);
        aq[s][2] = tf32r(Ps[r0 * PS_STR + 8 * s + tig + 4] * 0.125f);
        aq[s][3] = tf32r(Ps[r1 * PS_STR + 8 * s + tig + 4] * 0.125f);
    }

    float oc[8][4];
#pragma unroll
    for (int nt = 0; nt < 8; nt++) { oc[nt][0]=0.f; oc[nt][1]=0.f; oc[nt][2]=0.f; oc[nt][3]=0.f; }
    float m0 = -1e30f, m1 = -1e30f, l0 = 0.f, l1 = 0.f;
    const int qg0 = q0 + wm + grp, qg1 = qg0 + 8;

    for (int ti = 0; ti < ntl; ti++) {
        if (ti + 1 < ntl) { APREF(ti + 1, (ti + 1) & 1); cpa_wait1(); }
        else              { cpa_wait0(); }
        __syncthreads();

        const float* Ksb = sm + (ti & 1) * 64 * KS_STR;
        const float* Vsb = sm + OFF_V + (ti & 1) * 64 * VS_STR;
        const int j0 = j0s + ti * 64;

        // ---- S = Q @ K^T --------------------------------------------------
        float sc[8][4];
#pragma unroll
        for (int nt = 0; nt < 8; nt++) { sc[nt][0]=0.f; sc[nt][1]=0.f; sc[nt][2]=0.f; sc[nt][3]=0.f; }
#pragma unroll
        for (int s = 0; s < 8; s++) {
#pragma unroll
            for (int nt = 0; nt < 8; nt++) {
                float bb[2];
                bb[0] = tf32r(Ksb[(8 * nt + grp) * KS_STR + 8 * s + tig    ]);
                bb[1] = tf32r(Ksb[(8 * nt + grp) * KS_STR + 8 * s + tig + 4]);
                mma_tf32(sc[nt], aq[s], bb);
            }
        }

        // ---- mask + online softmax ---------------------------------------
        float tm0 = -1e30f, tm1 = -1e30f;
#pragma unroll
        for (int nt = 0; nt < 8; nt++) {
            const int ja = j0 + 8 * nt + 2 * tig;
            const int jb = ja + 1;
            if (ja >= SS || abs(qg0 - ja) > w) sc[nt][0] = -1e30f;
            if (jb >= SS || abs(qg0 - jb) > w) sc[nt][1] = -1e30f;
            if (ja >= SS || abs(qg1 - ja) > w) sc[nt][2] = -1e30f;
            if (jb >= SS || abs(qg1 - jb) > w) sc[nt][3] = -1e30f;
            tm0 = fmaxf(tm0, fmaxf(sc[nt][0], sc[nt][1]));
            tm1 = fmaxf(tm1, fmaxf(sc[nt][2], sc[nt][3]));
        }
        tm0 = fmaxf(tm0, __shfl_xor_sync(0xffffffffu, tm0, 1));
        tm0 = fmaxf(tm0, __shfl_xor_sync(0xffffffffu, tm0, 2));
        tm1 = fmaxf(tm1, __shfl_xor_sync(0xffffffffu, tm1, 1));
        tm1 = fmaxf(tm1, __shfl_xor_sync(0xffffffffu, tm1, 2));
        const float mn0 = fmaxf(m0, tm0), mn1 = fmaxf(m1, tm1);
        const float cf0 = __expf(m0 - mn0), cf1 = __expf(m1 - mn1);
        l0 *= cf0; l1 *= cf1;
#pragma unroll
        for (int nt = 0; nt < 8; nt++) {
            oc[nt][0] *= cf0; oc[nt][1] *= cf0;
            oc[nt][2] *= cf1; oc[nt][3] *= cf1;
        }
        float rs0 = 0.f, rs1 = 0.f;
#pragma unroll
        for (int nt = 0; nt < 8; nt++) {
            const float p00 = __expf(sc[nt][0] - mn0);
            const float p01 = __expf(sc[nt][1] - mn0);
            const float p10 = __expf(sc[nt][2] - mn1);
            const float p11 = __expf(sc[nt][3] - mn1);
            rs0 += p00 + p01; rs1 += p10 + p11;
            float2 w0; w0.x = tf32r(p00); w0.y = tf32r(p01);
            float2 w1; w1.x = tf32r(p10); w1.y = tf32r(p11);
            *(float2*)&Ps[r0 * PS_STR + 8 * nt + 2 * tig] = w0;
            *(float2*)&Ps[r1 * PS_STR + 8 * nt + 2 * tig] = w1;
        }
        rs0 += __shfl_xor_sync(0xffffffffu, rs0, 1);
        rs0 += __shfl_xor_sync(0xffffffffu, rs0, 2);
        rs1 += __shfl_xor_sync(0xffffffffu, rs1, 1);
        rs1 += __shfl_xor_sync(0xffffffffu, rs1, 2);
        l0 += rs0; l1 += rs1;
        m0 = mn0; m1 = mn1;
        __syncwarp();   // P rows are warp-private

        // ---- O += P @ V ---------------------------------------------------
#pragma unroll
        for (int s = 0; s < 8; s++) {
            float ap[4];
            ap[0] = Ps[r0 * PS_STR + 8 * s + tig];
            ap[1] = Ps[r1 * PS_STR + 8 * s + tig];
            ap[2] = Ps[r0 * PS_STR + 8 * s + tig + 4];
            ap[3] = Ps[r1 * PS_STR + 8 * s + tig + 4];
#pragma unroll
            for (int nt = 0; nt < 8; nt++) {
                float bb[2];
                bb[0] = tf32r(Vsb[(8 * s + tig    ) * VS_STR + 8 * nt + grp]);
                bb[1] = tf32r(Vsb[(8 * s + tig + 4) * VS_STR + 8 * nt + grp]);
                mma_tf32(oc[nt], ap, bb);
            }
        }
        __syncthreads();   // everyone done with this K/V buf before it refills
    }

    const float inv0 = 1.f / l0, inv1 = 1.f / l1;
    float* o0 = ctx + ((size_t)(b * SS + qg0)) * DD + h * 64;
    float* o1 = ctx + ((size_t)(b * SS + qg1)) * DD + h * 64;
#pragma unroll
    for (int nt = 0; nt < 8; nt++) {
        const int d = 8 * nt + 2 * tig;
        float2 a; a.x = oc[nt][0] * inv0; a.y = oc[nt][1] * inv0;
        float2 c; c.x = oc[nt][2] * inv1; c.y = oc[nt][3] * inv1;
        *(float2*)(o0 + d) = a;
        *(float2*)(o1 + d) = c;
    }
}

// ---------------- LayerNorm (one block per row, D=512) ----------------------
__global__ __launch_bounds__(128)
void ln_kernel(const float* __restrict__ in, const float* __restrict__ g,
               const float* __restrict__ b, float* __restrict__ out)
{
    __shared__ float red[4];
    const int row = blockIdx.x;
    const int t = threadIdx.x;
    float4 v = ((const float4*)(in + (size_t)row * DD))[t];

    float s = v.x + v.y + v.z + v.w;
#pragma unroll
    for (int o1 = 16; o1; o1 >>= 1) s += __shfl_xor_sync(0xffffffffu, s, o1);
    if ((t & 31) == 0) red[t >> 5] = s;
    __syncthreads();
    const float mean = (red[0] + red[1] + red[2] + red[3]) * (1.f / 512.f);

    const float dx0 = v.x - mean, dx1 = v.y - mean, dx2 = v.z - mean, dx3 = v.w - mean;
    float sq = dx0*dx0 + dx1*dx1 + dx2*dx2 + dx3*dx3;
#pragma unroll
    for (int o1 = 16; o1; o1 >>= 1) sq += __shfl_xor_sync(0xffffffffu, sq, o1);
    __syncthreads();
    if ((t & 31) == 0) red[t >> 5] = sq;
    __syncthreads();
    const float var = (red[0] + red[1] + red[2] + red[3]) * (1.f / 512.f);
    const float rs = rsqrtf(var + 1e-5f);

    float4 gv = ((const float4*)g)[t];
    float4 bv = ((const float4*)b)[t];
    float4 ov;
    ov.x = dx0 * rs * gv.x + bv.x;
    ov.y = dx1 * rs * gv.y + bv.y;
    ov.z = dx2 * rs * gv.z + bv.z;
    ov.w = dx3 * rs * gv.w + bv.w;
    ((float4*)(out + (size_t)row * DD))[t] = ov;
}

// ---------------- launch ----------------------------------------------------
extern "C" void kernel_launch(void* const* d_in, const int* in_sizes, int n_in,
                              void* d_out, int out_size)
{
    const float* x     = (const float*)d_in[0];
    const float* w_in  = (const float*)d_in[1];
    const float* b_in  = (const float*)d_in[2];
    const float* w_out = (const float*)d_in[3];
    const float* b_out = (const float*)d_in[4];
    const float* ln1g  = (const float*)d_in[5];
    const float* ln1b  = (const float*)d_in[6];
    const float* ln2g  = (const float*)d_in[7];
    const float* ln2b  = (const float*)d_in[8];
    const float* w1    = (const float*)d_in[9];
    const float* b1    = (const float*)d_in[10];
    const float* w2    = (const float*)d_in[11];
    const float* b2    = (const float*)d_in[12];
    const int*   wnd   = (const int*)d_in[13];

    float *qkv, *ctx, *r1, *hbuf, *mid;
    cudaGetSymbolAddress((void**)&qkv,  g_qkv);
    cudaGetSymbolAddress((void**)&ctx,  g_ctx);
    cudaGetSymbolAddress((void**)&r1,   g_r1);
    cudaGetSymbolAddress((void**)&hbuf, g_h);
    cudaGetSymbolAddress((void**)&mid,  g_mid);

    cudaFuncSetAttribute(gemm_mma<0>, cudaFuncAttributeMaxDynamicSharedMemorySize, GEMM_SMEM);
    cudaFuncSetAttribute(gemm_mma<1>, cudaFuncAttributeMaxDynamicSharedMemorySize, GEMM_SMEM);
    cudaFuncSetAttribute(gemm_mma<2>, cudaFuncAttributeMaxDynamicSharedMemorySize, GEMM_SMEM);
    cudaFuncSetAttribute(attn_mma,    cudaFuncAttributeMaxDynamicSharedMemorySize, ATT_SMEM);

    // 1) fused QKV projection
    gemm_mma<0><<<dim3(12, 64), 256, GEMM_SMEM>>>(x, w_in, b_in, nullptr, qkv, MM, 1536, DD);
    // 2) sliding-window flash attention
    attn_mma<<<dim3(SS / 64, HH, BB), 128, ATT_SMEM>>>(qkv, ctx, wnd);
    // 3) out_proj + residual(x)
    gemm_mma<1><<<dim3(4, 64), 256, GEMM_SMEM>>>(ctx, w_out, b_out, x, r1, MM, DD, DD);
    // 4) LN1
    ln_kernel<<<MM, 128>>>(r1, ln1g, ln1b, hbuf);
    // 5) MLP fc1 + relu
    gemm_mma<2><<<dim3(4, 64), 256, GEMM_SMEM>>>(hbuf, w1, b1, nullptr, mid, MM, DD, DD);
    // 6) MLP fc2 + residual(h)
    gemm_mma<1><<<dim3(4, 64), 256, GEMM_SMEM>>>(mid, w2, b2, hbuf, r1, MM, DD, DD);
    // 7) LN2 -> output
    ln_kernel<<<MM, 128>>>(r1, ln2g, ln2b, (float*)d_out);
}

// round 7
// speedup vs baseline: 2.8296x; 1.1987x over previous
#include <cuda_runtime.h>
#include <cstdint>
#include <math.h>

// Problem constants (fixed shapes per reference)
#define BB   2
#define SS   4096
#define DD   512
#define HH   8
#define DHH  64
#define MM   (BB*SS)      // 8192 rows

// ---------------- scratch (device globals; no allocations allowed) ----------
__device__ float    g_qkv[MM * 1536];           // fp32 (attention input)
__device__ float    g_r1 [MM * DD];             // pre-LN buffer (reused)
__device__ float    g_h  [MM * DD];             // LN1 out fp32 (MLP residual)
__device__ uint32_t g_xbf   [MM * DD / 2];      // bf16x2 shadows
__device__ uint32_t g_ctxbf [MM * DD / 2];
__device__ uint32_t g_hbf   [MM * DD / 2];
__device__ uint32_t g_midbf [MM * DD / 2];
__device__ uint32_t g_winbf [1536 * DD / 2];
__device__ uint32_t g_woutbf[DD * DD / 2];
__device__ uint32_t g_w1bf  [DD * DD / 2];
__device__ uint32_t g_w2bf  [DD * DD / 2];

// ---------------- helpers ----------------------------------------------------
__device__ __forceinline__ float tf32r(float x) {
    float y; asm("cvt.rna.tf32.f32 %0, %1;" : "=f"(y) : "f"(x)); return y;
}
__device__ __forceinline__ uint32_t bfpack(float lo, float hi) {
    uint32_t r; asm("cvt.rn.bf16x2.f32 %0, %1, %2;" : "=r"(r) : "f"(hi), "f"(lo)); return r;
}

__device__ __forceinline__ void mma_tf32(float* d, const float* a, const float* b) {
    asm volatile(
        "mma.sync.aligned.m16n8k8.row.col.f32.tf32.tf32.f32 "
        "{%0,%1,%2,%3}, {%4,%5,%6,%7}, {%8,%9}, {%0,%1,%2,%3};"
        : "+f"(d[0]), "+f"(d[1]), "+f"(d[2]), "+f"(d[3])
        : "r"(__float_as_uint(a[0])), "r"(__float_as_uint(a[1])),
          "r"(__float_as_uint(a[2])), "r"(__float_as_uint(a[3])),
          "r"(__float_as_uint(b[0])), "r"(__float_as_uint(b[1])));
}
__device__ __forceinline__ void mma_bf16(float* d, const uint32_t* a, const uint32_t* b) {
    asm volatile(
        "mma.sync.aligned.m16n8k16.row.col.f32.bf16.bf16.f32 "
        "{%0,%1,%2,%3}, {%4,%5,%6,%7}, {%8,%9}, {%0,%1,%2,%3};"
        : "+f"(d[0]), "+f"(d[1]), "+f"(d[2]), "+f"(d[3])
        : "r"(a[0]), "r"(a[1]), "r"(a[2]), "r"(a[3]),
          "r"(b[0]), "r"(b[1]));
}

__device__ __forceinline__ void cpa16(uint32_t d, const void* s) {
    asm volatile("cp.async.ca.shared.global [%0], [%1], 16;" :: "r"(d), "l"(s));
}
__device__ __forceinline__ void cpa16z(uint32_t d, const void* s, int sz) {
    asm volatile("cp.async.ca.shared.global [%0], [%1], 16, %2;" :: "r"(d), "l"(s), "r"(sz));
}
__device__ __forceinline__ void cpa_commit() { asm volatile("cp.async.commit_group;" ::: "memory"); }
__device__ __forceinline__ void cpa_wait1()  { asm volatile("cp.async.wait_group 1;" ::: "memory"); }
__device__ __forceinline__ void cpa_wait0()  { asm volatile("cp.async.wait_group 0;" ::: "memory"); }

// ---------------- fp32 -> bf16x2 conversion ---------------------------------
__global__ __launch_bounds__(256)
void cvtbf_kernel(const float* __restrict__ in, uint32_t* __restrict__ out, int n4)
{
    const int i = blockIdx.x * 256 + threadIdx.x;
    if (i < n4) {
        float4 v = ((const float4*)in)[i];
        uint2 p;
        p.x = bfpack(v.x, v.y);
        p.y = bfpack(v.z, v.w);
        ((uint2*)out)[i] = p;
    }
}

// ================= bf16 mma.sync GEMM (cp.async 3-stage) =====================
// C = A @ W^T + bias (+epilogue). A:[M,K] bf16, W:[N,K] bf16. K mult of 32.
// Tile 128x128, BK=32 bf16, smem row stride 40 bf16 (conflict-free frags).
// MODE 0: fp32 out +bias; MODE 1: fp32 out +bias+resid; MODE 2: bf16 out +bias+relu
#define GSLOT  (128*40)                    // bf16 elems per matrix per stage
#define GEMM_SMEM (3 * GSLOT * 2 * 2)      // 61440 bytes

template<int MODE>
__global__ __launch_bounds__(256)
void gemm_bf(const uint32_t* __restrict__ Abf, const uint32_t* __restrict__ Wbf,
             const float* __restrict__ bias, const float* __restrict__ resid,
             void* __restrict__ Cout, int M, int N, int K)
{
    extern __shared__ __align__(16) uint16_t gsm[];   // bf16 raw
    uint16_t* As = gsm;                    // [3][128][40]
    uint16_t* Ws = gsm + 3 * GSLOT;

    const int t    = threadIdx.x;
    const int warp = t >> 5;
    const int lane = t & 31;
    const int grp  = lane >> 2;
    const int tig  = lane & 3;
    const int wm   = (warp >> 1) * 32;
    const int wn   = (warp & 1) * 64;
    const int brow = blockIdx.y * 128;
    const int bcol = blockIdx.x * 128;

    // staging: thread t -> matrix (t>>7), row (t&127), 4 x 16B chunks
    const int mat = t >> 7;
    const int sr  = t & 127;
    const uint16_t* gsrcA = (const uint16_t*)(mat ? (const void*)Wbf : (const void*)Abf);
    const int gbase = (mat ? bcol : brow) + sr;
    const uint16_t* gp = gsrcA + (size_t)gbase * K;
    const uint32_t sdst = (uint32_t)__cvta_generic_to_shared(
        (mat ? Ws : As) + sr * 40);

    const int NS = K >> 5;    // K/32 stages

#define GPREF(s) do { \
        const uint32_t _d = sdst + ((s) % 3) * (GSLOT * 2); \
        const uint16_t* _g = gp + (s) * 32; \
        cpa16(_d,      _g); \
        cpa16(_d + 16, _g + 8); \
        cpa16(_d + 32, _g + 16); \
        cpa16(_d + 48, _g + 24); \
        cpa_commit(); \
    } while (0)

    GPREF(0);
    GPREF(1);

    float acc[2][8][4];
#pragma unroll
    for (int mt = 0; mt < 2; mt++)
#pragma unroll
        for (int nt = 0; nt < 8; nt++)
#pragma unroll
            for (int r = 0; r < 4; r++) acc[mt][nt][r] = 0.f;

    for (int s = 0; s < NS; s++) {
        if (s == NS - 1) cpa_wait0(); else cpa_wait1();
        __syncthreads();
        if (s + 2 < NS) GPREF(s + 2);

        const uint16_t* Ab = As + (s % 3) * GSLOT;
        const uint16_t* Wb = Ws + (s % 3) * GSLOT;
#pragma unroll
        for (int ks = 0; ks < 2; ks++) {
            const int ko = 16 * ks;
            uint32_t afr[2][4];
#pragma unroll
            for (int mt = 0; mt < 2; mt++) {
                const int rb = wm + mt * 16;
                afr[mt][0] = *(const uint32_t*)&Ab[(rb + grp    ) * 40 + ko + tig * 2    ];
                afr[mt][1] = *(const uint32_t*)&Ab[(rb + grp + 8) * 40 + ko + tig * 2    ];
                afr[mt][2] = *(const uint32_t*)&Ab[(rb + grp    ) * 40 + ko + tig * 2 + 8];
                afr[mt][3] = *(const uint32_t*)&Ab[(rb + grp + 8) * 40 + ko + tig * 2 + 8];
            }
            uint32_t bfr[8][2];
#pragma unroll
            for (int nt = 0; nt < 8; nt++) {
                const int nb = wn + nt * 8 + grp;
                bfr[nt][0] = *(const uint32_t*)&Wb[nb * 40 + ko + tig * 2    ];
                bfr[nt][1] = *(const uint32_t*)&Wb[nb * 40 + ko + tig * 2 + 8];
            }
#pragma unroll
            for (int mt = 0; mt < 2; mt++)
#pragma unroll
                for (int nt = 0; nt < 8; nt++)
                    mma_bf16(acc[mt][nt], afr[mt], bfr[nt]);
        }
    }

    // epilogue
#pragma unroll
    for (int mt = 0; mt < 2; mt++) {
#pragma unroll
        for (int half = 0; half < 2; half++) {
            const int grow = brow + wm + 16 * mt + grp + 8 * half;
            const float* rrow = (MODE == 1) ? (resid + (size_t)grow * N + bcol) : nullptr;
#pragma unroll
            for (int nt = 0; nt < 8; nt++) {
                const int col = wn + 8 * nt + 2 * tig;
                float ox = acc[mt][nt][2 * half + 0] + bias[bcol + col];
                float oy = acc[mt][nt][2 * half + 1] + bias[bcol + col + 1];
                if (MODE == 1) {
                    const float2 rv = *(const float2*)(rrow + col);
                    ox += rv.x; oy += rv.y;
                }
                if (MODE == 2) {
                    ox = fmaxf(ox, 0.f); oy = fmaxf(oy, 0.f);
                    ((uint32_t*)Cout)[((size_t)grow * N + bcol + col) >> 1] = bfpack(ox, oy);
                } else {
                    float2 o; o.x = ox; o.y = oy;
                    *(float2*)((float*)Cout + (size_t)grow * N + bcol + col) = o;
                }
            }
        }
    }
}

// ============ sliding-window flash attention, tf32 mma + cp.async ============
// Q tile 64 rows, 4 warps. K/V double-buffered via cp.async; Q staged via Ps.
// Output written as bf16 (consumed by out_proj GEMM).
#define KS_STR 68
#define VS_STR 76
#define PS_STR 68
#define OFF_V  (2*64*KS_STR)
#define OFF_P  (OFF_V + 2*64*VS_STR)
#define ATT_SMEM ((OFF_P + 64*PS_STR) * 4)    // 91136 bytes

__global__ __launch_bounds__(128)
void attn_mma(const float* __restrict__ qkv, uint32_t* __restrict__ ctxbf,
              const int* __restrict__ wptr)
{
    extern __shared__ float sm[];
    float* Ps = sm + OFF_P;

    int w = *wptr;
    if (w < 0 || w > 1000000) w = (int)__int_as_float((unsigned)w);

    const int t    = threadIdx.x;
    const int warp = t >> 5;
    const int lane = t & 31;
    const int grp  = lane >> 2;
    const int tig  = lane & 3;
    const int wm   = warp * 16;
    const int q0   = blockIdx.x * 64;
    const int h    = blockIdx.y;
    const int b    = blockIdx.z;

    const uint32_t smb = (uint32_t)__cvta_generic_to_shared(sm);

    int j0s = q0 - w; if (j0s < 0) j0s = 0; j0s &= ~63;
    int jend = q0 + 64 + w; if (jend > SS) jend = SS;
    const int ntl = (jend - j0s + 63) >> 6;

    const int pr  = t & 63;
    const int isV = t >> 6;
#define APREF(ti, buf) do { \
        const int _jr = j0s + (ti) * 64 + pr; \
        const int _sz = (_jr < SS) ? 16 : 0; \
        const int _jc = (_jr < SS) ? _jr : (SS - 1); \
        const float* _src = qkv + ((size_t)(b * SS + _jc)) * 1536 + 512 + isV * 512 + h * 64; \
        const uint32_t _dst = smb + 4u * (isV ? (OFF_V + (buf) * 64 * VS_STR + pr * VS_STR) \
                                              : ((buf) * 64 * KS_STR + pr * KS_STR)); \
        _Pragma("unroll") \
        for (int _ci = 0; _ci < 16; _ci++) cpa16z(_dst + 16 * _ci, _src + 4 * _ci, _sz); \
        cpa_commit(); \
    } while (0)

    {
        const int r = t >> 1, c0 = (t & 1) * 32;
        const float* qp = qkv + ((size_t)(b * SS + q0 + r)) * 1536 + h * 64 + c0;
#pragma unroll
        for (int i = 0; i < 8; i++)
            *(float4*)&Ps[r * PS_STR + c0 + 4 * i] = *(const float4*)(qp + 4 * i);
    }
    APREF(0, 0);
    __syncthreads();

    const int r0 = wm + grp, r1 = r0 + 8;
    float aq[8][4];
#pragma unroll
    for (int s = 0; s < 8; s++) {
        aq[s][0] = tf32r(Ps[r0 * PS_STR + 8 * s + tig    ] * 0.125f);
        aq[s][1] = tf32r(Ps[r1 * PS_STR + 8 * s + tig    ] * 0.125f);
        aq[s][2] = tf32r(Ps[r0 * PS_STR + 8 * s + tig + 4] * 0.125f);
        aq[s][3] = tf32r(Ps[r1 * PS_STR + 8 * s + tig + 4] * 0.125f);
    }

    float oc[8][4];
#pragma unroll
    for (int nt = 0; nt < 8; nt++) { oc[nt][0]=0.f; oc[nt][1]=0.f; oc[nt][2]=0.f; oc[nt][3]=0.f; }
    float m0 = -1e30f, m1 = -1e30f, l0 = 0.f, l1 = 0.f;
    const int qg0 = q0 + wm + grp, qg1 = qg0 + 8;

    for (int ti = 0; ti < ntl; ti++) {
        if (ti + 1 < ntl) { APREF(ti + 1, (ti + 1) & 1); cpa_wait1(); }
        else              { cpa_wait0(); }
        __syncthreads();

        const float* Ksb = sm + (ti & 1) * 64 * KS_STR;
        const float* Vsb = sm + OFF_V + (ti & 1) * 64 * VS_STR;
        const int j0 = j0s + ti * 64;

        float sc[8][4];
#pragma unroll
        for (int nt = 0; nt < 8; nt++) { sc[nt][0]=0.f; sc[nt][1]=0.f; sc[nt][2]=0.f; sc[nt][3]=0.f; }
#pragma unroll
        for (int s = 0; s < 8; s++) {
#pragma unroll
            for (int nt = 0; nt < 8; nt++) {
                float bb[2];
                bb[0] = tf32r(Ksb[(8 * nt + grp) * KS_STR + 8 * s + tig    ]);
                bb[1] = tf32r(Ksb[(8 * nt + grp) * KS_STR + 8 * s + tig + 4]);
                mma_tf32(sc[nt], aq[s], bb);
            }
        }

        float tm0 = -1e30f, tm1 = -1e30f;
#pragma unroll
        for (int nt = 0; nt < 8; nt++) {
            const int ja = j0 + 8 * nt + 2 * tig;
            const int jb = ja + 1;
            if (ja >= SS || abs(qg0 - ja) > w) sc[nt][0] = -1e30f;
            if (jb >= SS || abs(qg0 - jb) > w) sc[nt][1] = -1e30f;
            if (ja >= SS || abs(qg1 - ja) > w) sc[nt][2] = -1e30f;
            if (jb >= SS || abs(qg1 - jb) > w) sc[nt][3] = -1e30f;
            tm0 = fmaxf(tm0, fmaxf(sc[nt][0], sc[nt][1]));
            tm1 = fmaxf(tm1, fmaxf(sc[nt][2], sc[nt][3]));
        }
        tm0 = fmaxf(tm0, __shfl_xor_sync(0xffffffffu, tm0, 1));
        tm0 = fmaxf(tm0, __shfl_xor_sync(0xffffffffu, tm0, 2));
        tm1 = fmaxf(tm1, __shfl_xor_sync(0xffffffffu, tm1, 1));
        tm1 = fmaxf(tm1, __shfl_xor_sync(0xffffffffu, tm1, 2));
        const float mn0 = fmaxf(m0, tm0), mn1 = fmaxf(m1, tm1);
        const float cf0 = __expf(m0 - mn0), cf1 = __expf(m1 - mn1);
        l0 *= cf0; l1 *= cf1;
#pragma unroll
        for (int nt = 0; nt < 8; nt++) {
            oc[nt][0] *= cf0; oc[nt][1] *= cf0;
            oc[nt][2] *= cf1; oc[nt][3] *= cf1;
        }
        float rs0 = 0.f, rs1 = 0.f;
#pragma unroll
        for (int nt = 0; nt < 8; nt++) {
            const float p00 = __expf(sc[nt][0] - mn0);
            const float p01 = __expf(sc[nt][1] - mn0);
            const float p10 = __expf(sc[nt][2] - mn1);
            const float p11 = __expf(sc[nt][3] - mn1);
            rs0 += p00 + p01; rs1 += p10 + p11;
            float2 w0; w0.x = tf32r(p00); w0.y = tf32r(p01);
            float2 w1; w1.x = tf32r(p10); w1.y = tf32r(p11);
            *(float2*)&Ps[r0 * PS_STR + 8 * nt + 2 * tig] = w0;
            *(float2*)&Ps[r1 * PS_STR + 8 * nt + 2 * tig] = w1;
        }
        rs0 += __shfl_xor_sync(0xffffffffu, rs0, 1);
        rs0 += __shfl_xor_sync(0xffffffffu, rs0, 2);
        rs1 += __shfl_xor_sync(0xffffffffu, rs1, 1);
        rs1 += __shfl_xor_sync(0xffffffffu, rs1, 2);
        l0 += rs0; l1 += rs1;
        m0 = mn0; m1 = mn1;
        __syncwarp();

#pragma unroll
        for (int s = 0; s < 8; s++) {
            float ap[4];
            ap[0] = Ps[r0 * PS_STR + 8 * s + tig];
            ap[1] = Ps[r1 * PS_STR + 8 * s + tig];
            ap[2] = Ps[r0 * PS_STR + 8 * s + tig + 4];
            ap[3] = Ps[r1 * PS_STR + 8 * s + tig + 4];
#pragma unroll
            for (int nt = 0; nt < 8; nt++) {
                float bb[2];
                bb[0] = tf32r(Vsb[(8 * s + tig    ) * VS_STR + 8 * nt + grp]);
                bb[1] = tf32r(Vsb[(8 * s + tig + 4) * VS_STR + 8 * nt + grp]);
                mma_tf32(oc[nt], ap, bb);
            }
        }
        __syncthreads();
    }

    const float inv0 = 1.f / l0, inv1 = 1.f / l1;
    uint32_t* c0p = ctxbf + (((size_t)(b * SS + qg0)) * DD + h * 64) / 2;
    uint32_t* c1p = ctxbf + (((size_t)(b * SS + qg1)) * DD + h * 64) / 2;
#pragma unroll
    for (int nt = 0; nt < 8; nt++) {
        const int d = 8 * nt + 2 * tig;
        c0p[d >> 1] = bfpack(oc[nt][0] * inv0, oc[nt][1] * inv0);
        c1p[d >> 1] = bfpack(oc[nt][2] * inv1, oc[nt][3] * inv1);
    }
}

// ---------------- LayerNorm (one block per row, D=512) ----------------------
// Writes fp32 out; optionally also a bf16 shadow (for next GEMM's A input).
__global__ __launch_bounds__(128)
void ln_kernel(const float* __restrict__ in, const float* __restrict__ g,
               const float* __restrict__ b, float* __restrict__ out,
               uint32_t* __restrict__ outbf)
{
    __shared__ float red[4];
    const int row = blockIdx.x;
    const int t = threadIdx.x;
    float4 v = ((const float4*)(in + (size_t)row * DD))[t];

    float s = v.x + v.y + v.z + v.w;
#pragma unroll
    for (int o1 = 16; o1; o1 >>= 1) s += __shfl_xor_sync(0xffffffffu, s, o1);
    if ((t & 31) == 0) red[t >> 5] = s;
    __syncthreads();
    const float mean = (red[0] + red[1] + red[2] + red[3]) * (1.f / 512.f);

    const float dx0 = v.x - mean, dx1 = v.y - mean, dx2 = v.z - mean, dx3 = v.w - mean;
    float sq = dx0*dx0 + dx1*dx1 + dx2*dx2 + dx3*dx3;
#pragma unroll
    for (int o1 = 16; o1; o1 >>= 1) sq += __shfl_xor_sync(0xffffffffu, sq, o1);
    __syncthreads();
    if ((t & 31) == 0) red[t >> 5] = sq;
    __syncthreads();
    const float var = (red[0] + red[1] + red[2] + red[3]) * (1.f / 512.f);
    const float rs = rsqrtf(var + 1e-5f);

    float4 gv = ((const float4*)g)[t];
    float4 bv = ((const float4*)b)[t];
    float4 ov;
    ov.x = dx0 * rs * gv.x + bv.x;
    ov.y = dx1 * rs * gv.y + bv.y;
    ov.z = dx2 * rs * gv.z + bv.z;
    ov.w = dx3 * rs * gv.w + bv.w;
    ((float4*)(out + (size_t)row * DD))[t] = ov;
    if (outbf) {
        uint2 p;
        p.x = bfpack(ov.x, ov.y);
        p.y = bfpack(ov.z, ov.w);
        ((uint2*)(outbf + (size_t)row * DD / 2))[t] = p;
    }
}

// ---------------- launch ----------------------------------------------------
extern "C" void kernel_launch(void* const* d_in, const int* in_sizes, int n_in,
                              void* d_out, int out_size)
{
    const float* x     = (const float*)d_in[0];
    const float* w_in  = (const float*)d_in[1];
    const float* b_in  = (const float*)d_in[2];
    const float* w_out = (const float*)d_in[3];
    const float* b_out = (const float*)d_in[4];
    const float* ln1g  = (const float*)d_in[5];
    const float* ln1b  = (const float*)d_in[6];
    const float* ln2g  = (const float*)d_in[7];
    const float* ln2b  = (const float*)d_in[8];
    const float* w1    = (const float*)d_in[9];
    const float* b1    = (const float*)d_in[10];
    const float* w2    = (const float*)d_in[11];
    const float* b2    = (const float*)d_in[12];
    const int*   wnd   = (const int*)d_in[13];

    float *qkv, *r1, *hbuf;
    uint32_t *xbf, *ctxbf, *hbf, *midbf, *winbf, *woutbf, *w1bf, *w2bf;
    cudaGetSymbolAddress((void**)&qkv,    g_qkv);
    cudaGetSymbolAddress((void**)&r1,     g_r1);
    cudaGetSymbolAddress((void**)&hbuf,   g_h);
    cudaGetSymbolAddress((void**)&xbf,    g_xbf);
    cudaGetSymbolAddress((void**)&ctxbf,  g_ctxbf);
    cudaGetSymbolAddress((void**)&hbf,    g_hbf);
    cudaGetSymbolAddress((void**)&midbf,  g_midbf);
    cudaGetSymbolAddress((void**)&winbf,  g_winbf);
    cudaGetSymbolAddress((void**)&woutbf, g_woutbf);
    cudaGetSymbolAddress((void**)&w1bf,   g_w1bf);
    cudaGetSymbolAddress((void**)&w2bf,   g_w2bf);

    cudaFuncSetAttribute(gemm_bf<0>, cudaFuncAttributeMaxDynamicSharedMemorySize, GEMM_SMEM);
    cudaFuncSetAttribute(gemm_bf<1>, cudaFuncAttributeMaxDynamicSharedMemorySize, GEMM_SMEM);
    cudaFuncSetAttribute(gemm_bf<2>, cudaFuncAttributeMaxDynamicSharedMemorySize, GEMM_SMEM);
    cudaFuncSetAttribute(attn_mma,   cudaFuncAttributeMaxDynamicSharedMemorySize, ATT_SMEM);

    // 0) bf16 conversions (x + weights)
    cvtbf_kernel<<<(MM*DD/4 + 255)/256, 256>>>(x,     xbf,    MM*DD/4);
    cvtbf_kernel<<<(1536*DD/4 + 255)/256, 256>>>(w_in, winbf,  1536*DD/4);
    cvtbf_kernel<<<(DD*DD/4 + 255)/256, 256>>>(w_out, woutbf, DD*DD/4);
    cvtbf_kernel<<<(DD*DD/4 + 255)/256, 256>>>(w1,    w1bf,   DD*DD/4);
    cvtbf_kernel<<<(DD*DD/4 + 255)/256, 256>>>(w2,    w2bf,   DD*DD/4);

    // 1) fused QKV projection (bf16 mma) -> fp32 qkv
    gemm_bf<0><<<dim3(12, 64), 256, GEMM_SMEM>>>(xbf, winbf, b_in, nullptr, qkv, MM, 1536, DD);
    // 2) sliding-window flash attention (tf32) -> bf16 ctx
    attn_mma<<<dim3(SS / 64, HH, BB), 128, ATT_SMEM>>>(qkv, ctxbf, wnd);
    // 3) out_proj + residual(x) -> fp32 r1
    gemm_bf<1><<<dim3(4, 64), 256, GEMM_SMEM>>>(ctxbf, woutbf, b_out, x, r1, MM, DD, DD);
    // 4) LN1 -> fp32 h + bf16 shadow
    ln_kernel<<<MM, 128>>>(r1, ln1g, ln1b, hbuf, hbf);
    // 5) MLP fc1 + relu -> bf16 mid
    gemm_bf<2><<<dim3(4, 64), 256, GEMM_SMEM>>>(hbf, w1bf, b1, nullptr, midbf, MM, DD, DD);
    // 6) MLP fc2 + residual(h) -> fp32 r1
    gemm_bf<1><<<dim3(4, 64), 256, GEMM_SMEM>>>(midbf, w2bf, b2, hbuf, r1, MM, DD, DD);
    // 7) LN2 -> output
    ln_kernel<<<MM, 128>>>(r1, ln2g, ln2b, (float*)d_out, nullptr);
}

// round 8
// speedup vs baseline: 3.1085x; 1.0986x over previous
#include <cuda_runtime.h>
#include <cstdint>
#include <math.h>

// Problem constants (fixed shapes per reference)
#define BB   2
#define SS   4096
#define DD   512
#define HH   8
#define DHH  64
#define MM   (BB*SS)      // 8192 rows

// ---------------- scratch (device globals; no allocations allowed) ----------
__device__ float    g_qkv[MM * 1536];           // fp32 (attention input)
__device__ float    g_r1 [MM * DD];             // pre-LN buffer (reused)
__device__ float    g_h  [MM * DD];             // LN1 out fp32 (MLP residual)
__device__ uint32_t g_xbf   [MM * DD / 2];      // bf16x2 shadows
__device__ uint32_t g_ctxbf [MM * DD / 2];
__device__ uint32_t g_hbf   [MM * DD / 2];
__device__ uint32_t g_midbf [MM * DD / 2];
__device__ uint32_t g_winbf [1536 * DD / 2];
__device__ uint32_t g_woutbf[DD * DD / 2];
__device__ uint32_t g_w1bf  [DD * DD / 2];
__device__ uint32_t g_w2bf  [DD * DD / 2];

// ---------------- helpers ----------------------------------------------------
__device__ __forceinline__ float tf32r(float x) {
    float y; asm("cvt.rna.tf32.f32 %0, %1;" : "=f"(y) : "f"(x)); return y;
}
__device__ __forceinline__ uint32_t bfpack(float lo, float hi) {
    uint32_t r; asm("cvt.rn.bf16x2.f32 %0, %1, %2;" : "=r"(r) : "f"(hi), "f"(lo)); return r;
}

__device__ __forceinline__ void mma_tf32(float* d, const float* a, const float* b) {
    asm volatile(
        "mma.sync.aligned.m16n8k8.row.col.f32.tf32.tf32.f32 "
        "{%0,%1,%2,%3}, {%4,%5,%6,%7}, {%8,%9}, {%0,%1,%2,%3};"
        : "+f"(d[0]), "+f"(d[1]), "+f"(d[2]), "+f"(d[3])
        : "r"(__float_as_uint(a[0])), "r"(__float_as_uint(a[1])),
          "r"(__float_as_uint(a[2])), "r"(__float_as_uint(a[3])),
          "r"(__float_as_uint(b[0])), "r"(__float_as_uint(b[1])));
}
__device__ __forceinline__ void mma_bf16(float* d, const uint32_t* a, const uint32_t* b) {
    asm volatile(
        "mma.sync.aligned.m16n8k16.row.col.f32.bf16.bf16.f32 "
        "{%0,%1,%2,%3}, {%4,%5,%6,%7}, {%8,%9}, {%0,%1,%2,%3};"
        : "+f"(d[0]), "+f"(d[1]), "+f"(d[2]), "+f"(d[3])
        : "r"(a[0]), "r"(a[1]), "r"(a[2]), "r"(a[3]),
          "r"(b[0]), "r"(b[1]));
}
__device__ __forceinline__ void ldsm_x4(uint32_t* r, uint32_t addr) {
    asm volatile("ldmatrix.sync.aligned.m8n8.x4.shared.b16 {%0,%1,%2,%3}, [%4];"
        : "=r"(r[0]), "=r"(r[1]), "=r"(r[2]), "=r"(r[3]) : "r"(addr));
}

__device__ __forceinline__ void cpa16(uint32_t d, const void* s) {
    asm volatile("cp.async.ca.shared.global [%0], [%1], 16;" :: "r"(d), "l"(s));
}
__device__ __forceinline__ void cpa16z(uint32_t d, const void* s, int sz) {
    asm volatile("cp.async.ca.shared.global [%0], [%1], 16, %2;" :: "r"(d), "l"(s), "r"(sz));
}
__device__ __forceinline__ void cpa_commit() { asm volatile("cp.async.commit_group;" ::: "memory"); }
__device__ __forceinline__ void cpa_wait1()  { asm volatile("cp.async.wait_group 1;" ::: "memory"); }
__device__ __forceinline__ void cpa_wait0()  { asm volatile("cp.async.wait_group 0;" ::: "memory"); }

// ---------------- fused fp32 -> bf16x2 conversion (all 5 tensors) -----------
// sizes in float4 units: x 1048576 | w_in 196608 | w_out/w1/w2 65536 each
#define CVT_N0 1048576
#define CVT_N1 (CVT_N0 + 196608)          // 1245184
#define CVT_N2 (CVT_N1 + 65536)           // 1310720
#define CVT_N3 (CVT_N2 + 65536)           // 1376256
#define CVT_TOT (CVT_N3 + 65536)          // 1441792  (divisible by 256)

__global__ __launch_bounds__(256)
void cvtbf_all(const float* __restrict__ x,    const float* __restrict__ win,
               const float* __restrict__ wout, const float* __restrict__ w1,
               const float* __restrict__ w2,
               uint32_t* __restrict__ xbf,    uint32_t* __restrict__ winbf,
               uint32_t* __restrict__ woutbf, uint32_t* __restrict__ w1bf,
               uint32_t* __restrict__ w2bf)
{
    const int i = blockIdx.x * 256 + threadIdx.x;
    const float* src; uint32_t* dst; int j;
    if (i < CVT_N0)      { src = x;    dst = xbf;    j = i; }
    else if (i < CVT_N1) { src = win;  dst = winbf;  j = i - CVT_N0; }
    else if (i < CVT_N2) { src = wout; dst = woutbf; j = i - CVT_N1; }
    else if (i < CVT_N3) { src = w1;   dst = w1bf;   j = i - CVT_N2; }
    else                 { src = w2;   dst = w2bf;   j = i - CVT_N3; }
    float4 v = ((const float4*)src)[j];
    uint2 p;
    p.x = bfpack(v.x, v.y);
    p.y = bfpack(v.z, v.w);
    ((uint2*)dst)[j] = p;
}

// ================= bf16 mma.sync GEMM (cp.async + ldmatrix) ==================
// C = A @ W^T + bias (+epilogue). A:[M,K] bf16, W:[N,K] bf16. K mult of 32.
// Tile 128x128, BK=32 bf16, smem row stride 40 bf16 (ldmatrix conflict-free).
// MODE 0: fp32 out +bias; MODE 1: fp32 out +bias+resid; MODE 2: bf16 out +bias+relu
#define GSLOT  (128*40)                    // bf16 elems per matrix per stage
#define GEMM_SMEM (3 * GSLOT * 2 * 2)      // 61440 bytes

template<int MODE>
__global__ __launch_bounds__(256)
void gemm_bf(const uint32_t* __restrict__ Abf, const uint32_t* __restrict__ Wbf,
             const float* __restrict__ bias, const float* __restrict__ resid,
             void* __restrict__ Cout, int M, int N, int K)
{
    extern __shared__ __align__(16) uint16_t gsm[];   // bf16 raw
    uint16_t* As = gsm;                    // [3][128][40]
    uint16_t* Ws = gsm + 3 * GSLOT;

    const int t    = threadIdx.x;
    const int warp = t >> 5;
    const int lane = t & 31;
    const int grp  = lane >> 2;
    const int tig  = lane & 3;
    const int wm   = (warp >> 1) * 32;
    const int wn   = (warp & 1) * 64;
    const int brow = blockIdx.y * 128;
    const int bcol = blockIdx.x * 128;

    // staging: thread t -> matrix (t>>7), row (t&127), 4 x 16B chunks
    const int mat = t >> 7;
    const int sr  = t & 127;
    const uint16_t* gsrcA = (const uint16_t*)(mat ? (const void*)Wbf : (const void*)Abf);
    const int gbase = (mat ? bcol : brow) + sr;
    const uint16_t* gp = gsrcA + (size_t)gbase * K;
    const uint32_t sdst = (uint32_t)__cvta_generic_to_shared(
        (mat ? Ws : As) + sr * 40);

    // ldmatrix per-lane addresses (byte offsets inside one stage slab)
    const uint32_t sm0 = (uint32_t)__cvta_generic_to_shared(gsm);
    uint32_t aoff[2], boff[4];
#pragma unroll
    for (int mt = 0; mt < 2; mt++)
        aoff[mt] = ((wm + mt * 16 + (lane & 15)) * 40 + ((lane >> 4) & 1) * 8) * 2;
#pragma unroll
    for (int p = 0; p < 4; p++)
        boff[p] = ((wn + 16 * p + (lane & 7) + ((lane >> 4) & 1) * 8) * 40
                   + ((lane >> 3) & 1) * 8) * 2 + 3 * GSLOT * 2;

    const int NS = K >> 5;    // K/32 stages

#define GPREF(s) do { \
        const uint32_t _d = sdst + ((s) % 3) * (GSLOT * 2); \
        const uint16_t* _g = gp + (s) * 32; \
        cpa16(_d,      _g); \
        cpa16(_d + 16, _g + 8); \
        cpa16(_d + 32, _g + 16); \
        cpa16(_d + 48, _g + 24); \
        cpa_commit(); \
    } while (0)

    GPREF(0);
    GPREF(1);

    float acc[2][8][4];
#pragma unroll
    for (int mt = 0; mt < 2; mt++)
#pragma unroll
        for (int nt = 0; nt < 8; nt++)
#pragma unroll
            for (int r = 0; r < 4; r++) acc[mt][nt][r] = 0.f;

    for (int s = 0; s < NS; s++) {
        if (s == NS - 1) cpa_wait0(); else cpa_wait1();
        __syncthreads();
        if (s + 2 < NS) GPREF(s + 2);

        const uint32_t stg = sm0 + (s % 3) * (GSLOT * 2);
#pragma unroll
        for (int ks = 0; ks < 2; ks++) {
            const uint32_t kb = stg + ks * 32;
            uint32_t afr[2][4];
            ldsm_x4(afr[0], kb + aoff[0]);
            ldsm_x4(afr[1], kb + aoff[1]);
            uint32_t bfr[8][2];
#pragma unroll
            for (int p = 0; p < 4; p++) {
                uint32_t bq[4];
                ldsm_x4(bq, kb + boff[p]);
                bfr[2*p  ][0] = bq[0]; bfr[2*p  ][1] = bq[1];
                bfr[2*p+1][0] = bq[2]; bfr[2*p+1][1] = bq[3];
            }
#pragma unroll
            for (int mt = 0; mt < 2; mt++)
#pragma unroll
                for (int nt = 0; nt < 8; nt++)
                    mma_bf16(acc[mt][nt], afr[mt], bfr[nt]);
        }
    }

    // epilogue
#pragma unroll
    for (int mt = 0; mt < 2; mt++) {
#pragma unroll
        for (int half = 0; half < 2; half++) {
            const int grow = brow + wm + 16 * mt + grp + 8 * half;
            const float* rrow = (MODE == 1) ? (resid + (size_t)grow * N + bcol) : nullptr;
#pragma unroll
            for (int nt = 0; nt < 8; nt++) {
                const int col = wn + 8 * nt + 2 * tig;
                float ox = acc[mt][nt][2 * half + 0] + bias[bcol + col];
                float oy = acc[mt][nt][2 * half + 1] + bias[bcol + col + 1];
                if (MODE == 1) {
                    const float2 rv = *(const float2*)(rrow + col);
                    ox += rv.x; oy += rv.y;
                }
                if (MODE == 2) {
                    ox = fmaxf(ox, 0.f); oy = fmaxf(oy, 0.f);
                    ((uint32_t*)Cout)[((size_t)grow * N + bcol + col) >> 1] = bfpack(ox, oy);
                } else {
                    float2 o; o.x = ox; o.y = oy;
                    *(float2*)((float*)Cout + (size_t)grow * N + bcol + col) = o;
                }
            }
        }
    }
}

// ============ sliding-window flash attention, tf32 mma + cp.async ============
// Q tile 64 rows, 4 warps. K/V double-buffered via cp.async; Q staged via Ps.
// Output written as bf16 (consumed by out_proj GEMM).
#define KS_STR 68
#define VS_STR 76
#define PS_STR 68
#define OFF_V  (2*64*KS_STR)
#define OFF_P  (OFF_V + 2*64*VS_STR)
#define ATT_SMEM ((OFF_P + 64*PS_STR) * 4)    // 91136 bytes

__global__ __launch_bounds__(128)
void attn_mma(const float* __restrict__ qkv, uint32_t* __restrict__ ctxbf,
              const int* __restrict__ wptr)
{
    extern __shared__ float sm[];
    float* Ps = sm + OFF_P;

    int w = *wptr;
    if (w < 0 || w > 1000000) w = (int)__int_as_float((unsigned)w);

    const int t    = threadIdx.x;
    const int warp = t >> 5;
    const int lane = t & 31;
    const int grp  = lane >> 2;
    const int tig  = lane & 3;
    const int wm   = warp * 16;
    const int q0   = blockIdx.x * 64;
    const int h    = blockIdx.y;
    const int b    = blockIdx.z;

    const uint32_t smb = (uint32_t)__cvta_generic_to_shared(sm);

    int j0s = q0 - w; if (j0s < 0) j0s = 0; j0s &= ~63;
    int jend = q0 + 64 + w; if (jend > SS) jend = SS;
    const int ntl = (jend - j0s + 63) >> 6;

    const int pr  = t & 63;
    const int isV = t >> 6;
#define APREF(ti, buf) do { \
        const int _jr = j0s + (ti) * 64 + pr; \
        const int _sz = (_jr < SS) ? 16 : 0; \
        const int _jc = (_jr < SS) ? _jr : (SS - 1); \
        const float* _src = qkv + ((size_t)(b * SS + _jc)) * 1536 + 512 + isV * 512 + h * 64; \
        const uint32_t _dst = smb + 4u * (isV ? (OFF_V + (buf) * 64 * VS_STR + pr * VS_STR) \
                                              : ((buf) * 64 * KS_STR + pr * KS_STR)); \
        _Pragma("unroll") \
        for (int _ci = 0; _ci < 16; _ci++) cpa16z(_dst + 16 * _ci, _src + 4 * _ci, _sz); \
        cpa_commit(); \
    } while (0)

    {
        const int r = t >> 1, c0 = (t & 1) * 32;
        const float* qp = qkv + ((size_t)(b * SS + q0 + r)) * 1536 + h * 64 + c0;
#pragma unroll
        for (int i = 0; i < 8; i++)
            *(float4*)&Ps[r * PS_STR + c0 + 4 * i] = *(const float4*)(qp + 4 * i);
    }
    APREF(0, 0);
    __syncthreads();

    const int r0 = wm + grp, r1 = r0 + 8;
    float aq[8][4];
#pragma unroll
    for (int s = 0; s < 8; s++) {
        aq[s][0] = tf32r(Ps[r0 * PS_STR + 8 * s + tig    ] * 0.125f);
        aq[s][1] = tf32r(Ps[r1 * PS_STR + 8 * s + tig    ] * 0.125f);
        aq[s][2] = tf32r(Ps[r0 * PS_STR + 8 * s + tig + 4] * 0.125f);
        aq[s][3] = tf32r(Ps[r1 * PS_STR + 8 * s + tig + 4] * 0.125f);
    }

    float oc[8][4];
#pragma unroll
    for (int nt = 0; nt < 8; nt++) { oc[nt][0]=0.f; oc[nt][1]=0.f; oc[nt][2]=0.f; oc[nt][3]=0.f; }
    float m0 = -1e30f, m1 = -1e30f, l0 = 0.f, l1 = 0.f;
    const int qg0 = q0 + wm + grp, qg1 = qg0 + 8;

    for (int ti = 0; ti < ntl; ti++) {
        if (ti + 1 < ntl) { APREF(ti + 1, (ti + 1) & 1); cpa_wait1(); }
        else              { cpa_wait0(); }
        __syncthreads();

        const float* Ksb = sm + (ti & 1) * 64 * KS_STR;
        const float* Vsb = sm + OFF_V + (ti & 1) * 64 * VS_STR;
        const int j0 = j0s + ti * 64;

        float sc[8][4];
#pragma unroll
        for (int nt = 0; nt < 8; nt++) { sc[nt][0]=0.f; sc[nt][1]=0.f; sc[nt][2]=0.f; sc[nt][3]=0.f; }
#pragma unroll
        for (int s = 0; s < 8; s++) {
#pragma unroll
            for (int nt = 0; nt < 8; nt++) {
                float bb[2];
                bb[0] = tf32r(Ksb[(8 * nt + grp) * KS_STR + 8 * s + tig    ]);
                bb[1] = tf32r(Ksb[(8 * nt + grp) * KS_STR + 8 * s + tig + 4]);
                mma_tf32(sc[nt], aq[s], bb);
            }
        }

        float tm0 = -1e30f, tm1 = -1e30f;
#pragma unroll
        for (int nt = 0; nt < 8; nt++) {
            const int ja = j0 + 8 * nt + 2 * tig;
            const int jb = ja + 1;
            if (ja >= SS || abs(qg0 - ja) > w) sc[nt][0] = -1e30f;
            if (jb >= SS || abs(qg0 - jb) > w) sc[nt][1] = -1e30f;
            if (ja >= SS || abs(qg1 - ja) > w) sc[nt][2] = -1e30f;
            if (jb >= SS || abs(qg1 - jb) > w) sc[nt][3] = -1e30f;
            tm0 = fmaxf(tm0, fmaxf(sc[nt][0], sc[nt][1]));
            tm1 = fmaxf(tm1, fmaxf(sc[nt][2], sc[nt][3]));
        }
        tm0 = fmaxf(tm0, __shfl_xor_sync(0xffffffffu, tm0, 1));
        tm0 = fmaxf(tm0, __shfl_xor_sync(0xffffffffu, tm0, 2));
        tm1 = fmaxf(tm1, __shfl_xor_sync(0xffffffffu, tm1, 1));
        tm1 = fmaxf(tm1, __shfl_xor_sync(0xffffffffu, tm1, 2));
        const float mn0 = fmaxf(m0, tm0), mn1 = fmaxf(m1, tm1);
        const float cf0 = __expf(m0 - mn0), cf1 = __expf(m1 - mn1);
        l0 *= cf0; l1 *= cf1;
#pragma unroll
        for (int nt = 0; nt < 8; nt++) {
            oc[nt][0] *= cf0; oc[nt][1] *= cf0;
            oc[nt][2] *= cf1; oc[nt][3] *= cf1;
        }
        float rs0 = 0.f, rs1 = 0.f;
#pragma unroll
        for (int nt = 0; nt < 8; nt++) {
            const float p00 = __expf(sc[nt][0] - mn0);
            const float p01 = __expf(sc[nt][1] - mn0);
            const float p10 = __expf(sc[nt][2] - mn1);
            const float p11 = __expf(sc[nt][3] - mn1);
            rs0 += p00 + p01; rs1 += p10 + p11;
            float2 w0; w0.x = tf32r(p00); w0.y = tf32r(p01);
            float2 w1; w1.x = tf32r(p10); w1.y = tf32r(p11);
            *(float2*)&Ps[r0 * PS_STR + 8 * nt + 2 * tig] = w0;
            *(float2*)&Ps[r1 * PS_STR + 8 * nt + 2 * tig] = w1;
        }
        rs0 += __shfl_xor_sync(0xffffffffu, rs0, 1);
        rs0 += __shfl_xor_sync(0xffffffffu, rs0, 2);
        rs1 += __shfl_xor_sync(0xffffffffu, rs1, 1);
        rs1 += __shfl_xor_sync(0xffffffffu, rs1, 2);
        l0 += rs0; l1 += rs1;
        m0 = mn0; m1 = mn1;
        __syncwarp();

#pragma unroll
        for (int s = 0; s < 8; s++) {
            float ap[4];
            ap[0] = Ps[r0 * PS_STR + 8 * s + tig];
            ap[1] = Ps[r1 * PS_STR + 8 * s + tig];
            ap[2] = Ps[r0 * PS_STR + 8 * s + tig + 4];
            ap[3] = Ps[r1 * PS_STR + 8 * s + tig + 4];
#pragma unroll
            for (int nt = 0; nt < 8; nt++) {
                float bb[2];
                bb[0] = tf32r(Vsb[(8 * s + tig    ) * VS_STR + 8 * nt + grp]);
                bb[1] = tf32r(Vsb[(8 * s + tig + 4) * VS_STR + 8 * nt + grp]);
                mma_tf32(oc[nt], ap, bb);
            }
        }
        __syncthreads();
    }

    const float inv0 = 1.f / l0, inv1 = 1.f / l1;
    uint32_t* c0p = ctxbf + (((size_t)(b * SS + qg0)) * DD + h * 64) / 2;
    uint32_t* c1p = ctxbf + (((size_t)(b * SS + qg1)) * DD + h * 64) / 2;
#pragma unroll
    for (int nt = 0; nt < 8; nt++) {
        const int d = 8 * nt + 2 * tig;
        c0p[d >> 1] = bfpack(oc[nt][0] * inv0, oc[nt][1] * inv0);
        c1p[d >> 1] = bfpack(oc[nt][2] * inv1, oc[nt][3] * inv1);
    }
}

// ---------------- LayerNorm (one block per row, D=512) ----------------------
__global__ __launch_bounds__(128)
void ln_kernel(const float* __restrict__ in, const float* __restrict__ g,
               const float* __restrict__ b, float* __restrict__ out,
               uint32_t* __restrict__ outbf)
{
    __shared__ float red[4];
    const int row = blockIdx.x;
    const int t = threadIdx.x;
    float4 v = ((const float4*)(in + (size_t)row * DD))[t];

    float s = v.x + v.y + v.z + v.w;
#pragma unroll
    for (int o1 = 16; o1; o1 >>= 1) s += __shfl_xor_sync(0xffffffffu, s, o1);
    if ((t & 31) == 0) red[t >> 5] = s;
    __syncthreads();
    const float mean = (red[0] + red[1] + red[2] + red[3]) * (1.f / 512.f);

    const float dx0 = v.x - mean, dx1 = v.y - mean, dx2 = v.z - mean, dx3 = v.w - mean;
    float sq = dx0*dx0 + dx1*dx1 + dx2*dx2 + dx3*dx3;
#pragma unroll
    for (int o1 = 16; o1; o1 >>= 1) sq += __shfl_xor_sync(0xffffffffu, sq, o1);
    __syncthreads();
    if ((t & 31) == 0) red[t >> 5] = sq;
    __syncthreads();
    const float var = (red[0] + red[1] + red[2] + red[3]) * (1.f / 512.f);
    const float rs = rsqrtf(var + 1e-5f);

    float4 gv = ((const float4*)g)[t];
    float4 bv = ((const float4*)b)[t];
    float4 ov;
    ov.x = dx0 * rs * gv.x + bv.x;
    ov.y = dx1 * rs * gv.y + bv.y;
    ov.z = dx2 * rs * gv.z + bv.z;
    ov.w = dx3 * rs * gv.w + bv.w;
    ((float4*)(out + (size_t)row * DD))[t] = ov;
    if (outbf) {
        uint2 p;
        p.x = bfpack(ov.x, ov.y);
        p.y = bfpack(ov.z, ov.w);
        ((uint2*)(outbf + (size_t)row * DD / 2))[t] = p;
    }
}

// ---------------- launch ----------------------------------------------------
extern "C" void kernel_launch(void* const* d_in, const int* in_sizes, int n_in,
                              void* d_out, int out_size)
{
    const float* x     = (const float*)d_in[0];
    const float* w_in  = (const float*)d_in[1];
    const float* b_in  = (const float*)d_in[2];
    const float* w_out = (const float*)d_in[3];
    const float* b_out = (const float*)d_in[4];
    const float* ln1g  = (const float*)d_in[5];
    const float* ln1b  = (const float*)d_in[6];
    const float* ln2g  = (const float*)d_in[7];
    const float* ln2b  = (const float*)d_in[8];
    const float* w1    = (const float*)d_in[9];
    const float* b1    = (const float*)d_in[10];
    const float* w2    = (const float*)d_in[11];
    const float* b2    = (const float*)d_in[12];
    const int*   wnd   = (const int*)d_in[13];

    float *qkv, *r1, *hbuf;
    uint32_t *xbf, *ctxbf, *hbf, *midbf, *winbf, *woutbf, *w1bf, *w2bf;
    cudaGetSymbolAddress((void**)&qkv,    g_qkv);
    cudaGetSymbolAddress((void**)&r1,     g_r1);
    cudaGetSymbolAddress((void**)&hbuf,   g_h);
    cudaGetSymbolAddress((void**)&xbf,    g_xbf);
    cudaGetSymbolAddress((void**)&ctxbf,  g_ctxbf);
    cudaGetSymbolAddress((void**)&hbf,    g_hbf);
    cudaGetSymbolAddress((void**)&midbf,  g_midbf);
    cudaGetSymbolAddress((void**)&winbf,  g_winbf);
    cudaGetSymbolAddress((void**)&woutbf, g_woutbf);
    cudaGetSymbolAddress((void**)&w1bf,   g_w1bf);
    cudaGetSymbolAddress((void**)&w2bf,   g_w2bf);

    cudaFuncSetAttribute(gemm_bf<0>, cudaFuncAttributeMaxDynamicSharedMemorySize, GEMM_SMEM);
    cudaFuncSetAttribute(gemm_bf<1>, cudaFuncAttributeMaxDynamicSharedMemorySize, GEMM_SMEM);
    cudaFuncSetAttribute(gemm_bf<2>, cudaFuncAttributeMaxDynamicSharedMemorySize, GEMM_SMEM);
    cudaFuncSetAttribute(attn_mma,   cudaFuncAttributeMaxDynamicSharedMemorySize, ATT_SMEM);

    // 0) fused bf16 conversions (x + all weights) — one launch
    cvtbf_all<<<CVT_TOT / 256, 256>>>(x, w_in, w_out, w1, w2,
                                      xbf, winbf, woutbf, w1bf, w2bf);

    // 1) fused QKV projection (bf16 mma + ldmatrix) -> fp32 qkv
    gemm_bf<0><<<dim3(12, 64), 256, GEMM_SMEM>>>(xbf, winbf, b_in, nullptr, qkv, MM, 1536, DD);
    // 2) sliding-window flash attention (tf32) -> bf16 ctx
    attn_mma<<<dim3(SS / 64, HH, BB), 128, ATT_SMEM>>>(qkv, ctxbf, wnd);
    // 3) out_proj + residual(x) -> fp32 r1
    gemm_bf<1><<<dim3(4, 64), 256, GEMM_SMEM>>>(ctxbf, woutbf, b_out, x, r1, MM, DD, DD);
    // 4) LN1 -> fp32 h + bf16 shadow
    ln_kernel<<<MM, 128>>>(r1, ln1g, ln1b, hbuf, hbf);
    // 5) MLP fc1 + relu -> bf16 mid
    gemm_bf<2><<<dim3(4, 64), 256, GEMM_SMEM>>>(hbf, w1bf, b1, nullptr, midbf, MM, DD, DD);
    // 6) MLP fc2 + residual(h) -> fp32 r1
    gemm_bf<1><<<dim3(4, 64), 256, GEMM_SMEM>>>(midbf, w2bf, b2, hbuf, r1, MM, DD, DD);
    // 7) LN2 -> output
    ln_kernel<<<MM, 128>>>(r1, ln2g, ln2b, (float*)d_out, nullptr);
}

// round 9
// speedup vs baseline: 4.6062x; 1.4818x over previous
#include <cuda_runtime.h>
#include <cstdint>
#include <math.h>

// Problem constants (fixed shapes per reference)
#define BB   2
#define SS   4096
#define DD   512
#define HH   8
#define DHH  64
#define MM   (BB*SS)      // 8192 rows

// ---------------- scratch (device globals; no allocations allowed) ----------
__device__ uint16_t g_qkvbf[MM * 1536];         // bf16 qkv (attention input)
__device__ float    g_r1 [MM * DD];             // pre-LN buffer (reused)
__device__ float    g_h  [MM * DD];             // LN1 out fp32 (MLP residual)
__device__ uint32_t g_xbf   [MM * DD / 2];      // bf16x2 shadows
__device__ uint32_t g_ctxbf [MM * DD / 2];
__device__ uint32_t g_hbf   [MM * DD / 2];
__device__ uint32_t g_midbf [MM * DD / 2];
__device__ uint32_t g_winbf [1536 * DD / 2];
__device__ uint32_t g_woutbf[DD * DD / 2];
__device__ uint32_t g_w1bf  [DD * DD / 2];
__device__ uint32_t g_w2bf  [DD * DD / 2];

// ---------------- helpers ----------------------------------------------------
__device__ __forceinline__ uint32_t bfpack(float lo, float hi) {
    uint32_t r; asm("cvt.rn.bf16x2.f32 %0, %1, %2;" : "=r"(r) : "f"(hi), "f"(lo)); return r;
}
__device__ __forceinline__ void mma_bf16(float* d, const uint32_t* a, const uint32_t* b) {
    asm volatile(
        "mma.sync.aligned.m16n8k16.row.col.f32.bf16.bf16.f32 "
        "{%0,%1,%2,%3}, {%4,%5,%6,%7}, {%8,%9}, {%0,%1,%2,%3};"
        : "+f"(d[0]), "+f"(d[1]), "+f"(d[2]), "+f"(d[3])
        : "r"(a[0]), "r"(a[1]), "r"(a[2]), "r"(a[3]),
          "r"(b[0]), "r"(b[1]));
}
__device__ __forceinline__ void ldsm_x4(uint32_t* r, uint32_t addr) {
    asm volatile("ldmatrix.sync.aligned.m8n8.x4.shared.b16 {%0,%1,%2,%3}, [%4];"
        : "=r"(r[0]), "=r"(r[1]), "=r"(r[2]), "=r"(r[3]) : "r"(addr));
}
__device__ __forceinline__ void ldsm_x4t(uint32_t* r, uint32_t addr) {
    asm volatile("ldmatrix.sync.aligned.m8n8.x4.trans.shared.b16 {%0,%1,%2,%3}, [%4];"
        : "=r"(r[0]), "=r"(r[1]), "=r"(r[2]), "=r"(r[3]) : "r"(addr));
}
__device__ __forceinline__ void cpa16(uint32_t d, const void* s) {
    asm volatile("cp.async.ca.shared.global [%0], [%1], 16;" :: "r"(d), "l"(s));
}
__device__ __forceinline__ void cpa16z(uint32_t d, const void* s, int sz) {
    asm volatile("cp.async.ca.shared.global [%0], [%1], 16, %2;" :: "r"(d), "l"(s), "r"(sz));
}
__device__ __forceinline__ void cpa_commit() { asm volatile("cp.async.commit_group;" ::: "memory"); }
__device__ __forceinline__ void cpa_wait1()  { asm volatile("cp.async.wait_group 1;" ::: "memory"); }
__device__ __forceinline__ void cpa_wait0()  { asm volatile("cp.async.wait_group 0;" ::: "memory"); }

// ---------------- fused fp32 -> bf16x2 conversion (all 5 tensors) -----------
#define CVT_N0 1048576
#define CVT_N1 (CVT_N0 + 196608)
#define CVT_N2 (CVT_N1 + 65536)
#define CVT_N3 (CVT_N2 + 65536)
#define CVT_TOT (CVT_N3 + 65536)

__global__ __launch_bounds__(256)
void cvtbf_all(const float* __restrict__ x,    const float* __restrict__ win,
               const float* __restrict__ wout, const float* __restrict__ w1,
               const float* __restrict__ w2,
               uint32_t* __restrict__ xbf,    uint32_t* __restrict__ winbf,
               uint32_t* __restrict__ woutbf, uint32_t* __restrict__ w1bf,
               uint32_t* __restrict__ w2bf)
{
    const int i = blockIdx.x * 256 + threadIdx.x;
    const float* src; uint32_t* dst; int j;
    if (i < CVT_N0)      { src = x;    dst = xbf;    j = i; }
    else if (i < CVT_N1) { src = win;  dst = winbf;  j = i - CVT_N0; }
    else if (i < CVT_N2) { src = wout; dst = woutbf; j = i - CVT_N1; }
    else if (i < CVT_N3) { src = w1;   dst = w1bf;   j = i - CVT_N2; }
    else                 { src = w2;   dst = w2bf;   j = i - CVT_N3; }
    float4 v = ((const float4*)src)[j];
    uint2 p;
    p.x = bfpack(v.x, v.y);
    p.y = bfpack(v.z, v.w);
    ((uint2*)dst)[j] = p;
}

// ================= bf16 mma GEMM: 4 warps, 64x64 warp tile ===================
// C = A @ W^T + bias (+epilogue). A:[M,K] bf16, W:[N,K] bf16. K mult of 32.
// CTA tile 128x128 (warp grid 2x2), BK=32, smem row stride 40 bf16.
// MODE 1: fp32 +bias+resid; MODE 2: bf16 +bias+relu; MODE 3: bf16 +bias
#define GSLOT  (128*40)
#define GEMM_SMEM (3 * GSLOT * 2 * 2)      // 61440 bytes

template<int MODE>
__global__ __launch_bounds__(128)
void gemm_bf(const uint32_t* __restrict__ Abf, const uint32_t* __restrict__ Wbf,
             const float* __restrict__ bias, const float* __restrict__ resid,
             void* __restrict__ Cout, int M, int N, int K)
{
    extern __shared__ __align__(16) uint16_t gsm[];
    uint16_t* As = gsm;                    // [3][128][40]
    uint16_t* Ws = gsm + 3 * GSLOT;

    const int t    = threadIdx.x;
    const int warp = t >> 5;
    const int lane = t & 31;
    const int grp  = lane >> 2;
    const int tig  = lane & 3;
    const int wm   = (warp >> 1) * 64;     // 2 warps in m
    const int wn   = (warp & 1) * 64;      // 2 warps in n
    const int brow = blockIdx.y * 128;
    const int bcol = blockIdx.x * 128;

    // staging: thread t -> matrix (t>>6), rows 2*(t&63), 2*(t&63)+1
    const int mat = t >> 6;
    const int r2  = (t & 63) * 2;
    const uint16_t* gp = (const uint16_t*)(mat ? (const void*)Wbf : (const void*)Abf)
                         + (size_t)((mat ? bcol : brow) + r2) * K;
    const uint32_t sdst = (uint32_t)__cvta_generic_to_shared((mat ? Ws : As) + r2 * 40);

    const uint32_t sm0 = (uint32_t)__cvta_generic_to_shared(gsm);
    uint32_t aoff[4], boff[4];
#pragma unroll
    for (int mt = 0; mt < 4; mt++)
        aoff[mt] = ((wm + mt * 16 + (lane & 15)) * 40 + ((lane >> 4) & 1) * 8) * 2;
#pragma unroll
    for (int p = 0; p < 4; p++)
        boff[p] = ((wn + 16 * p + (lane & 7) + ((lane >> 4) & 1) * 8) * 40
                   + ((lane >> 3) & 1) * 8) * 2 + 3 * GSLOT * 2;

    const int NS = K >> 5;

#define GPREF(s) do { \
        const uint32_t _d = sdst + ((s) % 3) * (GSLOT * 2); \
        const uint16_t* _g = gp + (s) * 32; \
        cpa16(_d,      _g);      cpa16(_d + 16, _g + 8); \
        cpa16(_d + 32, _g + 16); cpa16(_d + 48, _g + 24); \
        const uint16_t* _g2 = _g + K; \
        cpa16(_d + 80,  _g2);      cpa16(_d + 96,  _g2 + 8); \
        cpa16(_d + 112, _g2 + 16); cpa16(_d + 128, _g2 + 24); \
        cpa_commit(); \
    } while (0)

    GPREF(0);
    GPREF(1);

    float acc[4][8][4];
#pragma unroll
    for (int mt = 0; mt < 4; mt++)
#pragma unroll
        for (int nt = 0; nt < 8; nt++)
#pragma unroll
            for (int r = 0; r < 4; r++) acc[mt][nt][r] = 0.f;

    for (int s = 0; s < NS; s++) {
        if (s == NS - 1) cpa_wait0(); else cpa_wait1();
        __syncthreads();
        if (s + 2 < NS) GPREF(s + 2);

        const uint32_t stg = sm0 + (s % 3) * (GSLOT * 2);
#pragma unroll
        for (int ks = 0; ks < 2; ks++) {
            const uint32_t kb = stg + ks * 32;
            uint32_t afr[4][4];
#pragma unroll
            for (int mt = 0; mt < 4; mt++) ldsm_x4(afr[mt], kb + aoff[mt]);
            uint32_t bfr[8][2];
#pragma unroll
            for (int p = 0; p < 4; p++) {
                uint32_t bq[4];
                ldsm_x4(bq, kb + boff[p]);
                bfr[2*p  ][0] = bq[0]; bfr[2*p  ][1] = bq[1];
                bfr[2*p+1][0] = bq[2]; bfr[2*p+1][1] = bq[3];
            }
#pragma unroll
            for (int mt = 0; mt < 4; mt++)
#pragma unroll
                for (int nt = 0; nt < 8; nt++)
                    mma_bf16(acc[mt][nt], afr[mt], bfr[nt]);
        }
    }

    // epilogue
#pragma unroll
    for (int mt = 0; mt < 4; mt++) {
#pragma unroll
        for (int half = 0; half < 2; half++) {
            const int grow = brow + wm + 16 * mt + grp + 8 * half;
            const float* rrow = (MODE == 1) ? (resid + (size_t)grow * N + bcol) : nullptr;
#pragma unroll
            for (int nt = 0; nt < 8; nt++) {
                const int col = wn + 8 * nt + 2 * tig;
                float ox = acc[mt][nt][2 * half + 0] + bias[bcol + col];
                float oy = acc[mt][nt][2 * half + 1] + bias[bcol + col + 1];
                if (MODE == 1) {
                    const float2 rv = *(const float2*)(rrow + col);
                    ox += rv.x; oy += rv.y;
                    float2 o; o.x = ox; o.y = oy;
                    *(float2*)((float*)Cout + (size_t)grow * N + bcol + col) = o;
                } else {
                    if (MODE == 2) { ox = fmaxf(ox, 0.f); oy = fmaxf(oy, 0.f); }
                    ((uint32_t*)Cout)[((size_t)grow * N + bcol + col) >> 1] = bfpack(ox, oy);
                }
            }
        }
    }
}

// ============ sliding-window flash attention, full bf16 mma ==================
// Q tile 64 rows, 4 warps (16 rows each). P stays in registers (C->A repack).
// K B-frags: plain ldmatrix; V B-frags: ldmatrix.trans. Stride 72 conflict-free.
#define QK_STR 72
#define KVBUF  (64 * QK_STR)     // uint16 elems per buffer

__global__ __launch_bounds__(128)
void attn_bf(const uint16_t* __restrict__ qkv, uint32_t* __restrict__ ctxbf,
             const int* __restrict__ wptr)
{
    __shared__ __align__(16) uint16_t Qs[KVBUF];
    __shared__ __align__(16) uint16_t Ks[2][KVBUF];
    __shared__ __align__(16) uint16_t Vs[2][KVBUF];

    int w = *wptr;
    if (w < 0 || w > 1000000) w = (int)__int_as_float((unsigned)w);

    const int t    = threadIdx.x;
    const int warp = t >> 5;
    const int lane = t & 31;
    const int grp  = lane >> 2;
    const int tig  = lane & 3;
    const int wm   = warp * 16;
    const int q0   = blockIdx.x * 64;
    const int h    = blockIdx.y;
    const int b    = blockIdx.z;

    const uint32_t qsb = (uint32_t)__cvta_generic_to_shared(Qs);
    const uint32_t ksb = (uint32_t)__cvta_generic_to_shared(Ks);
    const uint32_t vsb = (uint32_t)__cvta_generic_to_shared(Vs);

    int j0s = q0 - w; if (j0s < 0) j0s = 0; j0s &= ~63;
    int jend = q0 + 64 + w; if (jend > SS) jend = SS;
    const int ntl = (jend - j0s + 63) >> 6;

    const int pr  = t & 63;
    const int isV = t >> 6;
#define APREF(ti, buf) do { \
        const int _jr = j0s + (ti) * 64 + pr; \
        const int _sz = (_jr < SS) ? 16 : 0; \
        const int _jc = (_jr < SS) ? _jr : (SS - 1); \
        const uint16_t* _src = qkv + ((size_t)(b * SS + _jc)) * 1536 + 512 + isV * 512 + h * 64; \
        const uint32_t _dst = (isV ? vsb : ksb) + (buf) * (KVBUF * 2) + pr * (QK_STR * 2); \
        _Pragma("unroll") \
        for (int _ci = 0; _ci < 8; _ci++) cpa16z(_dst + 16 * _ci, _src + 8 * _ci, _sz); \
        cpa_commit(); \
    } while (0)

    // stage Q (cp.async) + start tile-0 prefetch (same commit group)
    {
        const int qr = t >> 1, qh = (t & 1) * 32;
        const uint16_t* qp = qkv + ((size_t)(b * SS + q0 + qr)) * 1536 + h * 64 + qh;
        const uint32_t qd = qsb + (qr * QK_STR + qh) * 2;
#pragma unroll
        for (int i = 0; i < 4; i++) cpa16(qd + 16 * i, qp + 8 * i);
    }
    APREF(0, 0);
    cpa_wait0();
    __syncthreads();

    // Q A-fragments (registers, reused across all tiles)
    uint32_t aq[4][4];
#pragma unroll
    for (int kt = 0; kt < 4; kt++)
        ldsm_x4(aq[kt], qsb + ((wm + (lane & 15)) * QK_STR + kt * 16 + ((lane >> 4) & 1) * 8) * 2);

    // K/V per-lane ldmatrix offsets (within one buffer)
    uint32_t koff[4], voff[4];
#pragma unroll
    for (int p = 0; p < 4; p++) {
        koff[p] = ((16 * p + (lane & 7) + ((lane >> 4) & 1) * 8) * QK_STR
                   + ((lane >> 3) & 1) * 8) * 2;
        voff[p] = (((lane & 7) + ((lane >> 3) & 1) * 8) * QK_STR
                   + p * 16 + ((lane >> 4) & 1) * 8) * 2;
    }

    float oc[8][4];
#pragma unroll
    for (int nt = 0; nt < 8; nt++) { oc[nt][0]=0.f; oc[nt][1]=0.f; oc[nt][2]=0.f; oc[nt][3]=0.f; }
    float m0 = -1e30f, m1 = -1e30f, l0 = 0.f, l1 = 0.f;
    const int qg0 = q0 + wm + grp, qg1 = qg0 + 8;

    for (int ti = 0; ti < ntl; ti++) {
        if (ti + 1 < ntl) { APREF(ti + 1, (ti + 1) & 1); cpa_wait1(); }
        else              { cpa_wait0(); }
        __syncthreads();

        const uint32_t kbase = ksb + (ti & 1) * (KVBUF * 2);
        const uint32_t vbase = vsb + (ti & 1) * (KVBUF * 2);
        const int j0 = j0s + ti * 64;

        // ---- S = Q @ K^T (bf16) ------------------------------------------
        float sc[8][4];
#pragma unroll
        for (int nt = 0; nt < 8; nt++) { sc[nt][0]=0.f; sc[nt][1]=0.f; sc[nt][2]=0.f; sc[nt][3]=0.f; }
#pragma unroll
        for (int kd = 0; kd < 4; kd++) {
#pragma unroll
            for (int p = 0; p < 4; p++) {
                uint32_t bq[4];
                ldsm_x4(bq, kbase + koff[p] + kd * 32);
                uint32_t b0[2] = { bq[0], bq[1] };
                uint32_t b1[2] = { bq[2], bq[3] };
                mma_bf16(sc[2*p  ], aq[kd], b0);
                mma_bf16(sc[2*p+1], aq[kd], b1);
            }
        }

        // ---- scale + mask + online softmax -------------------------------
        float tm0 = -1e30f, tm1 = -1e30f;
#pragma unroll
        for (int nt = 0; nt < 8; nt++) {
            sc[nt][0] *= 0.125f; sc[nt][1] *= 0.125f;
            sc[nt][2] *= 0.125f; sc[nt][3] *= 0.125f;
            const int ja = j0 + 8 * nt + 2 * tig;
            const int jb = ja + 1;
            if (ja >= SS || abs(qg0 - ja) > w) sc[nt][0] = -1e30f;
            if (jb >= SS || abs(qg0 - jb) > w) sc[nt][1] = -1e30f;
            if (ja >= SS || abs(qg1 - ja) > w) sc[nt][2] = -1e30f;
            if (jb >= SS || abs(qg1 - jb) > w) sc[nt][3] = -1e30f;
            tm0 = fmaxf(tm0, fmaxf(sc[nt][0], sc[nt][1]));
            tm1 = fmaxf(tm1, fmaxf(sc[nt][2], sc[nt][3]));
        }
        tm0 = fmaxf(tm0, __shfl_xor_sync(0xffffffffu, tm0, 1));
        tm0 = fmaxf(tm0, __shfl_xor_sync(0xffffffffu, tm0, 2));
        tm1 = fmaxf(tm1, __shfl_xor_sync(0xffffffffu, tm1, 1));
        tm1 = fmaxf(tm1, __shfl_xor_sync(0xffffffffu, tm1, 2));
        const float mn0 = fmaxf(m0, tm0), mn1 = fmaxf(m1, tm1);
        const float cf0 = __expf(m0 - mn0), cf1 = __expf(m1 - mn1);
        l0 *= cf0; l1 *= cf1;
#pragma unroll
        for (int nt = 0; nt < 8; nt++) {
            oc[nt][0] *= cf0; oc[nt][1] *= cf0;
            oc[nt][2] *= cf1; oc[nt][3] *= cf1;
        }
        float rs0 = 0.f, rs1 = 0.f;
#pragma unroll
        for (int nt = 0; nt < 8; nt++) {
            sc[nt][0] = __expf(sc[nt][0] - mn0);
            sc[nt][1] = __expf(sc[nt][1] - mn0);
            sc[nt][2] = __expf(sc[nt][2] - mn1);
            sc[nt][3] = __expf(sc[nt][3] - mn1);
            rs0 += sc[nt][0] + sc[nt][1];
            rs1 += sc[nt][2] + sc[nt][3];
        }
        rs0 += __shfl_xor_sync(0xffffffffu, rs0, 1);
        rs0 += __shfl_xor_sync(0xffffffffu, rs0, 2);
        rs1 += __shfl_xor_sync(0xffffffffu, rs1, 1);
        rs1 += __shfl_xor_sync(0xffffffffu, rs1, 2);
        l0 += rs0; l1 += rs1;
        m0 = mn0; m1 = mn1;

        // ---- P C-frags -> A-frags entirely in registers ------------------
        uint32_t ap[4][4];
#pragma unroll
        for (int jt = 0; jt < 4; jt++) {
            ap[jt][0] = bfpack(sc[2*jt  ][0], sc[2*jt  ][1]);
            ap[jt][1] = bfpack(sc[2*jt  ][2], sc[2*jt  ][3]);
            ap[jt][2] = bfpack(sc[2*jt+1][0], sc[2*jt+1][1]);
            ap[jt][3] = bfpack(sc[2*jt+1][2], sc[2*jt+1][3]);
        }

        // ---- O += P @ V (V^T via ldmatrix.trans) -------------------------
#pragma unroll
        for (int jt = 0; jt < 4; jt++) {
            const uint32_t jb2 = vbase + jt * (16 * QK_STR * 2);
#pragma unroll
            for (int p = 0; p < 4; p++) {
                uint32_t bv[4];
                ldsm_x4t(bv, jb2 + voff[p]);
                uint32_t b0[2] = { bv[0], bv[1] };
                uint32_t b1[2] = { bv[2], bv[3] };
                mma_bf16(oc[2*p  ], ap[jt], b0);
                mma_bf16(oc[2*p+1], ap[jt], b1);
            }
        }
        __syncthreads();   // done with this K/V buffer before refill
    }

    const float inv0 = 1.f / l0, inv1 = 1.f / l1;
    uint32_t* c0p = ctxbf + (((size_t)(b * SS + qg0)) * DD + h * 64) / 2;
    uint32_t* c1p = ctxbf + (((size_t)(b * SS + qg1)) * DD + h * 64) / 2;
#pragma unroll
    for (int nt = 0; nt < 8; nt++) {
        const int d = 8 * nt + 2 * tig;
        c0p[d >> 1] = bfpack(oc[nt][0] * inv0, oc[nt][1] * inv0);
        c1p[d >> 1] = bfpack(oc[nt][2] * inv1, oc[nt][3] * inv1);
    }
}

// ---------------- LayerNorm (one block per row, D=512) ----------------------
__global__ __launch_bounds__(128)
void ln_kernel(const float* __restrict__ in, const float* __restrict__ g,
               const float* __restrict__ b, float* __restrict__ out,
               uint32_t* __restrict__ outbf)
{
    __shared__ float red[4];
    const int row = blockIdx.x;
    const int t = threadIdx.x;
    float4 v = ((const float4*)(in + (size_t)row * DD))[t];

    float s = v.x + v.y + v.z + v.w;
#pragma unroll
    for (int o1 = 16; o1; o1 >>= 1) s += __shfl_xor_sync(0xffffffffu, s, o1);
    if ((t & 31) == 0) red[t >> 5] = s;
    __syncthreads();
    const float mean = (red[0] + red[1] + red[2] + red[3]) * (1.f / 512.f);

    const float dx0 = v.x - mean, dx1 = v.y - mean, dx2 = v.z - mean, dx3 = v.w - mean;
    float sq = dx0*dx0 + dx1*dx1 + dx2*dx2 + dx3*dx3;
#pragma unroll
    for (int o1 = 16; o1; o1 >>= 1) sq += __shfl_xor_sync(0xffffffffu, sq, o1);
    __syncthreads();
    if ((t & 31) == 0) red[t >> 5] = sq;
    __syncthreads();
    const float var = (red[0] + red[1] + red[2] + red[3]) * (1.f / 512.f);
    const float rs = rsqrtf(var + 1e-5f);

    float4 gv = ((const float4*)g)[t];
    float4 bv = ((const float4*)b)[t];
    float4 ov;
    ov.x = dx0 * rs * gv.x + bv.x;
    ov.y = dx1 * rs * gv.y + bv.y;
    ov.z = dx2 * rs * gv.z + bv.z;
    ov.w = dx3 * rs * gv.w + bv.w;
    ((float4*)(out + (size_t)row * DD))[t] = ov;
    if (outbf) {
        uint2 p;
        p.x = bfpack(ov.x, ov.y);
        p.y = bfpack(ov.z, ov.w);
        ((uint2*)(outbf + (size_t)row * DD / 2))[t] = p;
    }
}

// ---------------- launch ----------------------------------------------------
extern "C" void kernel_launch(void* const* d_in, const int* in_sizes, int n_in,
                              void* d_out, int out_size)
{
    const float* x     = (const float*)d_in[0];
    const float* w_in  = (const float*)d_in[1];
    const float* b_in  = (const float*)d_in[2];
    const float* w_out = (const float*)d_in[3];
    const float* b_out = (const float*)d_in[4];
    const float* ln1g  = (const float*)d_in[5];
    const float* ln1b  = (const float*)d_in[6];
    const float* ln2g  = (const float*)d_in[7];
    const float* ln2b  = (const float*)d_in[8];
    const float* w1    = (const float*)d_in[9];
    const float* b1    = (const float*)d_in[10];
    const float* w2    = (const float*)d_in[11];
    const float* b2    = (const float*)d_in[12];
    const int*   wnd   = (const int*)d_in[13];

    float *r1, *hbuf;
    uint16_t* qkvbf;
    uint32_t *xbf, *ctxbf, *hbf, *midbf, *winbf, *woutbf, *w1bf, *w2bf;
    cudaGetSymbolAddress((void**)&qkvbf,  g_qkvbf);
    cudaGetSymbolAddress((void**)&r1,     g_r1);
    cudaGetSymbolAddress((void**)&hbuf,   g_h);
    cudaGetSymbolAddress((void**)&xbf,    g_xbf);
    cudaGetSymbolAddress((void**)&ctxbf,  g_ctxbf);
    cudaGetSymbolAddress((void**)&hbf,    g_hbf);
    cudaGetSymbolAddress((void**)&midbf,  g_midbf);
    cudaGetSymbolAddress((void**)&winbf,  g_winbf);
    cudaGetSymbolAddress((void**)&woutbf, g_woutbf);
    cudaGetSymbolAddress((void**)&w1bf,   g_w1bf);
    cudaGetSymbolAddress((void**)&w2bf,   g_w2bf);

    cudaFuncSetAttribute(gemm_bf<1>, cudaFuncAttributeMaxDynamicSharedMemorySize, GEMM_SMEM);
    cudaFuncSetAttribute(gemm_bf<2>, cudaFuncAttributeMaxDynamicSharedMemorySize, GEMM_SMEM);
    cudaFuncSetAttribute(gemm_bf<3>, cudaFuncAttributeMaxDynamicSharedMemorySize, GEMM_SMEM);

    // 0) fused bf16 conversions (x + all weights)
    cvtbf_all<<<CVT_TOT / 256, 256>>>(x, w_in, w_out, w1, w2,
                                      xbf, winbf, woutbf, w1bf, w2bf);
    // 1) fused QKV projection -> bf16 qkv
    gemm_bf<3><<<dim3(12, 64), 128, GEMM_SMEM>>>(xbf, winbf, b_in, nullptr, qkvbf, MM, 1536, DD);
    // 2) sliding-window flash attention (bf16) -> bf16 ctx
    attn_bf<<<dim3(SS / 64, HH, BB), 128>>>(qkvbf, ctxbf, wnd);
    // 3) out_proj + residual(x) -> fp32 r1
    gemm_bf<1><<<dim3(4, 64), 128, GEMM_SMEM>>>(ctxbf, woutbf, b_out, x, r1, MM, DD, DD);
    // 4) LN1 -> fp32 h + bf16 shadow
    ln_kernel<<<MM, 128>>>(r1, ln1g, ln1b, hbuf, hbf);
    // 5) MLP fc1 + relu -> bf16 mid
    gemm_bf<2><<<dim3(4, 64), 128, GEMM_SMEM>>>(hbf, w1bf, b1, nullptr, midbf, MM, DD, DD);
    // 6) MLP fc2 + residual(h) -> fp32 r1
    gemm_bf<1><<<dim3(4, 64), 128, GEMM_SMEM>>>(midbf, w2bf, b2, hbuf, r1, MM, DD, DD);
    // 7) LN2 -> output
    ln_kernel<<<MM, 128>>>(r1, ln2g, ln2b, (float*)d_out, nullptr);
}